// round 1
// baseline (speedup 1.0000x reference)
#include <cuda_runtime.h>
#include <cuda_bf16.h>

#define N_NODES 100000
#define N_EDGES 800000
#define IN_SIZE 256
#define OUT_SIZE 256

// Scratch: supp = x @ W  (100000 x 256 fp32 = 102.4 MB)
__device__ float g_supp[(size_t)N_NODES * OUT_SIZE];

// ---------------------------------------------------------------------------
// GEMM: supp = x @ W.  BM=128, BN=128, BK=8, 256 threads, 8x8 per thread.
// ---------------------------------------------------------------------------
__global__ __launch_bounds__(256) void gemm_kernel(const float* __restrict__ A,
                                                   const float* __restrict__ B) {
    __shared__ float As[8][128];   // [k][m] (transposed on store)
    __shared__ float Bs[8][128];   // [k][n]

    const int tile_m = blockIdx.x * 128;
    const int tile_n = blockIdx.y * 128;
    const int tid = threadIdx.x;

    const int tx = tid & 15;        // 0..15 -> n subtile
    const int ty = tid >> 4;        // 0..15 -> m subtile

    // A tile load mapping: 128 rows x 8 k, float4 per thread (2 threads/row)
    const int a_row = tid >> 1;
    const int a_k   = (tid & 1) * 4;
    // B tile load mapping: 8 k-rows x 128 n, float4 per thread
    const int b_k   = tid >> 5;
    const int b_col = (tid & 31) * 4;

    float acc[8][8];
#pragma unroll
    for (int i = 0; i < 8; i++)
#pragma unroll
        for (int j = 0; j < 8; j++) acc[i][j] = 0.0f;

    const int gm_a = tile_m + a_row;
    const bool a_ok = (gm_a < N_NODES);

    for (int k0 = 0; k0 < IN_SIZE; k0 += 8) {
        float4 av = make_float4(0.f, 0.f, 0.f, 0.f);
        if (a_ok)
            av = *reinterpret_cast<const float4*>(&A[(size_t)gm_a * IN_SIZE + k0 + a_k]);
        As[a_k + 0][a_row] = av.x;
        As[a_k + 1][a_row] = av.y;
        As[a_k + 2][a_row] = av.z;
        As[a_k + 3][a_row] = av.w;

        float4 bv = *reinterpret_cast<const float4*>(
            &B[(size_t)(k0 + b_k) * OUT_SIZE + tile_n + b_col]);
        *reinterpret_cast<float4*>(&Bs[b_k][b_col]) = bv;

        __syncthreads();

#pragma unroll
        for (int kk = 0; kk < 8; kk++) {
            float ar[8], br[8];
#pragma unroll
            for (int i = 0; i < 8; i++) ar[i] = As[kk][ty * 8 + i];
#pragma unroll
            for (int j = 0; j < 8; j++) br[j] = Bs[kk][tx * 8 + j];
#pragma unroll
            for (int i = 0; i < 8; i++)
#pragma unroll
                for (int j = 0; j < 8; j++) acc[i][j] = fmaf(ar[i], br[j], acc[i][j]);
        }
        __syncthreads();
    }

#pragma unroll
    for (int i = 0; i < 8; i++) {
        const int gm = tile_m + ty * 8 + i;
        if (gm < N_NODES) {
            float* dst = &g_supp[(size_t)gm * OUT_SIZE + tile_n + tx * 8];
            *reinterpret_cast<float4*>(dst + 0) =
                make_float4(acc[i][0], acc[i][1], acc[i][2], acc[i][3]);
            *reinterpret_cast<float4*>(dst + 4) =
                make_float4(acc[i][4], acc[i][5], acc[i][6], acc[i][7]);
        }
    }
}

// ---------------------------------------------------------------------------
// Initialize out[n][c] = bias[c]
// ---------------------------------------------------------------------------
__global__ void bias_init_kernel(const float* __restrict__ bias, float* __restrict__ out) {
    const int total4 = N_NODES * (OUT_SIZE / 4);
    for (int idx = blockIdx.x * blockDim.x + threadIdx.x; idx < total4;
         idx += gridDim.x * blockDim.x) {
        const int c4 = idx & (OUT_SIZE / 4 - 1);
        reinterpret_cast<float4*>(out)[idx] =
            reinterpret_cast<const float4*>(bias)[c4];
    }
}

// ---------------------------------------------------------------------------
// Scatter: one warp per edge.  out[dst] += supp[src] * w  (atomicAdd / RED)
// ---------------------------------------------------------------------------
__global__ __launch_bounds__(256) void scatter_kernel(const float* __restrict__ ew,
                                                      const int* __restrict__ esrc,
                                                      const int* __restrict__ edst,
                                                      float* __restrict__ out) {
    const int warp = (blockIdx.x * blockDim.x + threadIdx.x) >> 5;
    const int lane = threadIdx.x & 31;
    if (warp >= N_EDGES) return;

    const int s = esrc[warp];
    const int d = edst[warp];
    const float w = ew[warp];

    const float4* sp = reinterpret_cast<const float4*>(&g_supp[(size_t)s * OUT_SIZE]);
    float* op = &out[(size_t)d * OUT_SIZE];

#pragma unroll
    for (int h = 0; h < 2; h++) {
        const float4 v = sp[h * 32 + lane];
        const int base = (h * 32 + lane) * 4;
        atomicAdd(&op[base + 0], v.x * w);
        atomicAdd(&op[base + 1], v.y * w);
        atomicAdd(&op[base + 2], v.z * w);
        atomicAdd(&op[base + 3], v.w * w);
    }
}

// ---------------------------------------------------------------------------
extern "C" void kernel_launch(void* const* d_in, const int* in_sizes, int n_in,
                              void* d_out, int out_size) {
    const float* x      = (const float*)d_in[0];   // [N_NODES, IN_SIZE]
    const float* weight = (const float*)d_in[1];   // [IN_SIZE, OUT_SIZE]
    const float* bias   = (const float*)d_in[2];   // [1, OUT_SIZE]
    const float* ew     = (const float*)d_in[3];   // [N_EDGES]
    const int*   esrc   = (const int*)d_in[4];     // [N_EDGES]
    const int*   edst   = (const int*)d_in[5];     // [N_EDGES]
    float* out = (float*)d_out;                    // [N_NODES, OUT_SIZE]

    // 1) supp = x @ W
    dim3 ggrid((N_NODES + 127) / 128, OUT_SIZE / 128);
    gemm_kernel<<<ggrid, 256>>>(x, weight);

    // 2) out = bias (broadcast)
    bias_init_kernel<<<592, 256>>>(bias, out);

    // 3) out[dst] += supp[src] * w
    const int warps_per_block = 256 / 32;
    const int nblocks = (N_EDGES + warps_per_block - 1) / warps_per_block;
    scatter_kernel<<<nblocks, 256>>>(ew, esrc, edst, out);
}

// round 2
// speedup vs baseline: 1.5536x; 1.5536x over previous
#include <cuda_runtime.h>
#include <cuda_bf16.h>

#define N_NODES 100000
#define N_EDGES 800000
#define IN_SIZE 256
#define OUT_SIZE 256

// Scratch: supp = x @ W  (100000 x 256 fp32 = 102.4 MB)
__device__ float g_supp[(size_t)N_NODES * OUT_SIZE];

// ---------------------------------------------------------------------------
// GEMM: supp = x @ W.  BM=128, BN=128, BK=8, 256 threads, 8x8 per thread.
// Double-buffered smem, 2 CTAs/SM.
// ---------------------------------------------------------------------------
__global__ __launch_bounds__(256, 2) void gemm_kernel(const float* __restrict__ A,
                                                      const float* __restrict__ B) {
    __shared__ float As[2][8][128];   // [buf][k][m] (transposed on store)
    __shared__ float Bs[2][8][128];   // [buf][k][n]

    const int tile_m = blockIdx.x * 128;
    const int tile_n = blockIdx.y * 128;
    const int tid = threadIdx.x;

    const int tx = tid & 15;        // n subtile
    const int ty = tid >> 4;        // m subtile

    // A tile load mapping: 128 rows x 8 k, float4 per thread (2 threads/row)
    const int a_row = tid >> 1;
    const int a_k   = (tid & 1) * 4;
    // B tile load mapping: 8 k-rows x 128 n, float4 per thread
    const int b_k   = tid >> 5;
    const int b_col = (tid & 31) * 4;

    float acc[8][8];
#pragma unroll
    for (int i = 0; i < 8; i++)
#pragma unroll
        for (int j = 0; j < 8; j++) acc[i][j] = 0.0f;

    const int gm_a = tile_m + a_row;
    const bool a_ok = (gm_a < N_NODES);
    const float* a_ptr = &A[(size_t)gm_a * IN_SIZE + a_k];
    const float* b_ptr = &B[(size_t)b_k * OUT_SIZE + tile_n + b_col];

    // Prologue: load k0 = 0 into buffer 0
    float4 av = make_float4(0.f, 0.f, 0.f, 0.f);
    if (a_ok) av = *reinterpret_cast<const float4*>(a_ptr);
    float4 bv = *reinterpret_cast<const float4*>(b_ptr);

    As[0][a_k + 0][a_row] = av.x;
    As[0][a_k + 1][a_row] = av.y;
    As[0][a_k + 2][a_row] = av.z;
    As[0][a_k + 3][a_row] = av.w;
    *reinterpret_cast<float4*>(&Bs[0][b_k][b_col]) = bv;
    __syncthreads();

    int cur = 0;
    const int NTILES = IN_SIZE / 8;   // 32
    for (int t = 0; t < NTILES; t++) {
        // Prefetch next tile (global loads issued before compute)
        if (t + 1 < NTILES) {
            const int k0 = (t + 1) * 8;
            if (a_ok) av = *reinterpret_cast<const float4*>(a_ptr + k0);
            bv = *reinterpret_cast<const float4*>(b_ptr + (size_t)k0 * OUT_SIZE);
        }

        // Compute on current buffer
#pragma unroll
        for (int kk = 0; kk < 8; kk++) {
            float ar[8], br[8];
#pragma unroll
            for (int i = 0; i < 8; i++) ar[i] = As[cur][kk][ty * 8 + i];
#pragma unroll
            for (int j = 0; j < 8; j++) br[j] = Bs[cur][kk][tx * 8 + j];
#pragma unroll
            for (int i = 0; i < 8; i++)
#pragma unroll
                for (int j = 0; j < 8; j++) acc[i][j] = fmaf(ar[i], br[j], acc[i][j]);
        }

        // Store prefetched tile into the other buffer, single sync
        if (t + 1 < NTILES) {
            const int nxt = cur ^ 1;
            As[nxt][a_k + 0][a_row] = av.x;
            As[nxt][a_k + 1][a_row] = av.y;
            As[nxt][a_k + 2][a_row] = av.z;
            As[nxt][a_k + 3][a_row] = av.w;
            *reinterpret_cast<float4*>(&Bs[nxt][b_k][b_col]) = bv;
            __syncthreads();
            cur = nxt;
        }
    }

#pragma unroll
    for (int i = 0; i < 8; i++) {
        const int gm = tile_m + ty * 8 + i;
        if (gm < N_NODES) {
            float* dst = &g_supp[(size_t)gm * OUT_SIZE + tile_n + tx * 8];
            *reinterpret_cast<float4*>(dst + 0) =
                make_float4(acc[i][0], acc[i][1], acc[i][2], acc[i][3]);
            *reinterpret_cast<float4*>(dst + 4) =
                make_float4(acc[i][4], acc[i][5], acc[i][6], acc[i][7]);
        }
    }
}

// ---------------------------------------------------------------------------
// Initialize out[n][c] = bias[c]
// ---------------------------------------------------------------------------
__global__ void bias_init_kernel(const float* __restrict__ bias, float* __restrict__ out) {
    const int total4 = N_NODES * (OUT_SIZE / 4);
    for (int idx = blockIdx.x * blockDim.x + threadIdx.x; idx < total4;
         idx += gridDim.x * blockDim.x) {
        const int c4 = idx & (OUT_SIZE / 4 - 1);
        reinterpret_cast<float4*>(out)[idx] =
            reinterpret_cast<const float4*>(bias)[c4];
    }
}

// ---------------------------------------------------------------------------
// Vector atomic add: red.global.add.v4.f32 (sm_90+)
// ---------------------------------------------------------------------------
__device__ __forceinline__ void red_add_v4(float* addr, float a, float b, float c, float d) {
    asm volatile("red.global.add.v4.f32 [%0], {%1, %2, %3, %4};"
                 :: "l"(addr), "f"(a), "f"(b), "f"(c), "f"(d)
                 : "memory");
}

// ---------------------------------------------------------------------------
// Scatter: one warp per edge.  out[dst] += supp[src] * w
// ---------------------------------------------------------------------------
__global__ __launch_bounds__(256) void scatter_kernel(const float* __restrict__ ew,
                                                      const int* __restrict__ esrc,
                                                      const int* __restrict__ edst,
                                                      float* __restrict__ out) {
    const int warp = (blockIdx.x * blockDim.x + threadIdx.x) >> 5;
    const int lane = threadIdx.x & 31;
    if (warp >= N_EDGES) return;

    const int s = esrc[warp];
    const int d = edst[warp];
    const float w = ew[warp];

    const float4* sp = reinterpret_cast<const float4*>(&g_supp[(size_t)s * OUT_SIZE]);
    float* op = &out[(size_t)d * OUT_SIZE];

    // Load both halves first (MLP=2), then issue vector atomics
    const float4 v0 = sp[lane];
    const float4 v1 = sp[32 + lane];

    red_add_v4(op + lane * 4,        v0.x * w, v0.y * w, v0.z * w, v0.w * w);
    red_add_v4(op + (32 + lane) * 4, v1.x * w, v1.y * w, v1.z * w, v1.w * w);
}

// ---------------------------------------------------------------------------
extern "C" void kernel_launch(void* const* d_in, const int* in_sizes, int n_in,
                              void* d_out, int out_size) {
    const float* x      = (const float*)d_in[0];   // [N_NODES, IN_SIZE]
    const float* weight = (const float*)d_in[1];   // [IN_SIZE, OUT_SIZE]
    const float* bias   = (const float*)d_in[2];   // [1, OUT_SIZE]
    const float* ew     = (const float*)d_in[3];   // [N_EDGES]
    const int*   esrc   = (const int*)d_in[4];     // [N_EDGES]
    const int*   edst   = (const int*)d_in[5];     // [N_EDGES]
    float* out = (float*)d_out;                    // [N_NODES, OUT_SIZE]

    // 1) supp = x @ W
    dim3 ggrid((N_NODES + 127) / 128, OUT_SIZE / 128);
    gemm_kernel<<<ggrid, 256>>>(x, weight);

    // 2) out = bias (broadcast)
    bias_init_kernel<<<592, 256>>>(bias, out);

    // 3) out[dst] += supp[src] * w
    const int warps_per_block = 256 / 32;
    const int nblocks = (N_EDGES + warps_per_block - 1) / warps_per_block;
    scatter_kernel<<<nblocks, 256>>>(ew, esrc, edst, out);
}

// round 4
// speedup vs baseline: 2.1730x; 1.3986x over previous
#include <cuda_runtime.h>
#include <cuda_bf16.h>
#include <cstdint>

#define N_NODES 100000
#define N_EDGES 800000
#define IN_SIZE 256
#define OUT_SIZE 256

// ---------------------------------------------------------------------------
// Device scratch
// ---------------------------------------------------------------------------
__device__ __align__(128) float g_supp[(size_t)N_NODES * OUT_SIZE];       // x @ W
__device__ __align__(128) __nv_bfloat16 g_w_hi[IN_SIZE * OUT_SIZE];       // W hi [k][n]
__device__ __align__(128) __nv_bfloat16 g_w_lo[IN_SIZE * OUT_SIZE];      // W lo [k][n]

// ---------------------------------------------------------------------------
// Helpers
// ---------------------------------------------------------------------------
__device__ __forceinline__ uint32_t smem_u32(const void* p) {
    uint32_t a;
    asm("{ .reg .u64 t; cvta.to.shared.u64 t, %1; cvt.u32.u64 %0, t; }" : "=r"(a) : "l"(p));
    return a;
}

__device__ __forceinline__ void ldsm_x4(uint32_t* r, uint32_t addr) {
    asm volatile("ldmatrix.sync.aligned.m8n8.x4.shared.b16 {%0,%1,%2,%3}, [%4];"
                 : "=r"(r[0]), "=r"(r[1]), "=r"(r[2]), "=r"(r[3]) : "r"(addr));
}
__device__ __forceinline__ void ldsm_x4_t(uint32_t* r, uint32_t addr) {
    asm volatile("ldmatrix.sync.aligned.m8n8.x4.trans.shared.b16 {%0,%1,%2,%3}, [%4];"
                 : "=r"(r[0]), "=r"(r[1]), "=r"(r[2]), "=r"(r[3]) : "r"(addr));
}
__device__ __forceinline__ void mma_bf16(float* d, const uint32_t* a, const uint32_t* b) {
    asm volatile(
        "mma.sync.aligned.m16n8k16.row.col.f32.bf16.bf16.f32 "
        "{%0,%1,%2,%3}, {%4,%5,%6,%7}, {%8,%9}, {%0,%1,%2,%3};"
        : "+f"(d[0]), "+f"(d[1]), "+f"(d[2]), "+f"(d[3])
        : "r"(a[0]), "r"(a[1]), "r"(a[2]), "r"(a[3]), "r"(b[0]), "r"(b[1]));
}
__device__ __forceinline__ uint32_t bfpack(float x, float y) {
    __nv_bfloat162 t = __floats2bfloat162_rn(x, y);
    return *reinterpret_cast<uint32_t*>(&t);
}

// ---------------------------------------------------------------------------
// Prep: W[k][n] fp32 -> bf16 hi/lo split, same layout
// ---------------------------------------------------------------------------
__global__ void prep_w_kernel(const float* __restrict__ W) {
    const int idx = blockIdx.x * blockDim.x + threadIdx.x;   // k*256+n
    const float v = W[idx];
    const __nv_bfloat16 h = __float2bfloat16_rn(v);
    g_w_hi[idx] = h;
    g_w_lo[idx] = __float2bfloat16_rn(v - __bfloat162float(h));
}

// ---------------------------------------------------------------------------
// GEMM: supp = x @ W, HMMA bf16 3-term split, fp32 accum.
// CTA tile 128x128, warps 4(M)x2(N), warp tile 32x64, KC=32.
// ---------------------------------------------------------------------------
#define KC 32
#define LDA 40    // halves: 32 + 8 pad  (row = 80B, 16B-multiple)
#define LDB 136   // halves: 128 + 8 pad (row = 272B, 16B-multiple)

__global__ __launch_bounds__(256, 1) void gemm_hmma_kernel(const float* __restrict__ X) {
    __shared__ __align__(16) __nv_bfloat16 As_hi[128 * LDA];
    __shared__ __align__(16) __nv_bfloat16 As_lo[128 * LDA];
    __shared__ __align__(16) __nv_bfloat16 Bs_hi[KC * LDB];
    __shared__ __align__(16) __nv_bfloat16 Bs_lo[KC * LDB];

    const int tid = threadIdx.x;
    const int lane = tid & 31;
    const int w = tid >> 5;
    const int wm = w >> 1;        // 0..3
    const int wn = w & 1;         // 0..1
    const int tile_m = blockIdx.x * 128;
    const int tile_n = blockIdx.y * 128;

    const uint32_t as_hi = smem_u32(As_hi);
    const uint32_t as_lo = smem_u32(As_lo);
    const uint32_t bs_hi = smem_u32(Bs_hi);
    const uint32_t bs_lo = smem_u32(Bs_lo);

    float acc[2][8][4];
#pragma unroll
    for (int i = 0; i < 2; i++)
#pragma unroll
        for (int j = 0; j < 8; j++)
#pragma unroll
            for (int q = 0; q < 4; q++) acc[i][j][q] = 0.0f;

    // A load mapping: 128 rows x 8 float4 slots -> 1024 slots / 256 thr = 4 each
    const int a_row = tid >> 3;          // base row step 32 over i
    const int a_q = tid & 7;             // float4 slot (4 floats)
    // B load mapping: KC rows x 16 float4(bf16x8) slots -> 512 / 256 = 2 each
    const int b_row = tid >> 4;
    const int b_q = tid & 15;

    // ldmatrix source addresses (lane-dependent parts)
    const int lm_row = lane & 15;
    const int lm_coloff = (lane >> 4) * 8;   // halves

    for (int c = 0; c < IN_SIZE / KC; c++) {
        const int k0 = c * KC;

        // ---- stage gmem loads into regs
        float4 af[4];
#pragma unroll
        for (int i = 0; i < 4; i++) {
            const int row = a_row + i * 32;
            const int m = tile_m + row;
            af[i] = make_float4(0.f, 0.f, 0.f, 0.f);
            if (m < N_NODES)
                af[i] = *reinterpret_cast<const float4*>(&X[(size_t)m * IN_SIZE + k0 + a_q * 4]);
        }
        float4 bh[2], bl[2];
#pragma unroll
        for (int i = 0; i < 2; i++) {
            const int kr = b_row + i * 16;
            const size_t off = ((size_t)(k0 + kr) * OUT_SIZE + tile_n + b_q * 8) * 2;  // bytes
            bh[i] = *reinterpret_cast<const float4*>(reinterpret_cast<const char*>(g_w_hi) + off);
            bl[i] = *reinterpret_cast<const float4*>(reinterpret_cast<const char*>(g_w_lo) + off);
        }

        __syncthreads();   // previous iteration's compute done reading smem

        // ---- A: split + store (4 bf16 = 8B per slot)
#pragma unroll
        for (int i = 0; i < 4; i++) {
            const int row = a_row + i * 32;
            const float4 f = af[i];
            const float hx = __bfloat162float(__float2bfloat16_rn(f.x));
            const float hy = __bfloat162float(__float2bfloat16_rn(f.y));
            const float hz = __bfloat162float(__float2bfloat16_rn(f.z));
            const float hw = __bfloat162float(__float2bfloat16_rn(f.w));
            uint2 hv = make_uint2(bfpack(f.x, f.y), bfpack(f.z, f.w));
            uint2 lv = make_uint2(bfpack(f.x - hx, f.y - hy), bfpack(f.z - hz, f.w - hw));
            *reinterpret_cast<uint2*>(&As_hi[row * LDA + a_q * 4]) = hv;
            *reinterpret_cast<uint2*>(&As_lo[row * LDA + a_q * 4]) = lv;
        }
        // ---- B: straight bf16 copy
#pragma unroll
        for (int i = 0; i < 2; i++) {
            const int kr = b_row + i * 16;
            *reinterpret_cast<float4*>(&Bs_hi[kr * LDB + b_q * 8]) = bh[i];
            *reinterpret_cast<float4*>(&Bs_lo[kr * LDB + b_q * 8]) = bl[i];
        }

        __syncthreads();

        // ---- compute: 2 k-steps of 16
#pragma unroll
        for (int kk = 0; kk < 2; kk++) {
            const int ks = kk * 16;

            uint32_t a_hi[2][4], a_lo[2][4];
#pragma unroll
            for (int i = 0; i < 2; i++) {
                const uint32_t off =
                    ((uint32_t)(wm * 32 + i * 16 + lm_row) * LDA + ks + lm_coloff) * 2;
                ldsm_x4(a_hi[i], as_hi + off);
                ldsm_x4(a_lo[i], as_lo + off);
            }

            uint32_t b_hi[16], b_lo[16];
#pragma unroll
            for (int jj = 0; jj < 4; jj++) {
                const uint32_t off =
                    ((uint32_t)(ks + lm_row) * LDB + wn * 64 + jj * 16 + lm_coloff) * 2;
                ldsm_x4_t(&b_hi[jj * 4], bs_hi + off);
                ldsm_x4_t(&b_lo[jj * 4], bs_lo + off);
            }

#pragma unroll
            for (int i = 0; i < 2; i++)
#pragma unroll
                for (int j = 0; j < 8; j++) {
                    mma_bf16(acc[i][j], a_hi[i], &b_hi[j * 2]);
                    mma_bf16(acc[i][j], a_hi[i], &b_lo[j * 2]);
                    mma_bf16(acc[i][j], a_lo[i], &b_hi[j * 2]);
                }
        }
    }

    // ---- epilogue: acc -> g_supp
    const int er = lane >> 2;          // row within 8
    const int ec = (lane & 3) * 2;     // col pair
#pragma unroll
    for (int i = 0; i < 2; i++) {
        const int r0 = tile_m + wm * 32 + i * 16 + er;
#pragma unroll
        for (int j = 0; j < 8; j++) {
            const int col = tile_n + wn * 64 + j * 8 + ec;
            if (r0 < N_NODES)
                *reinterpret_cast<float2*>(&g_supp[(size_t)r0 * OUT_SIZE + col]) =
                    make_float2(acc[i][j][0], acc[i][j][1]);
            if (r0 + 8 < N_NODES)
                *reinterpret_cast<float2*>(&g_supp[(size_t)(r0 + 8) * OUT_SIZE + col]) =
                    make_float2(acc[i][j][2], acc[i][j][3]);
        }
    }
}

// ---------------------------------------------------------------------------
// out[n][c] = bias[c]
// ---------------------------------------------------------------------------
__global__ void bias_init_kernel(const float* __restrict__ bias, float* __restrict__ out) {
    const int total4 = N_NODES * (OUT_SIZE / 4);
    for (int idx = blockIdx.x * blockDim.x + threadIdx.x; idx < total4;
         idx += gridDim.x * blockDim.x) {
        const int c4 = idx & (OUT_SIZE / 4 - 1);
        reinterpret_cast<float4*>(out)[idx] = reinterpret_cast<const float4*>(bias)[c4];
    }
}

// ---------------------------------------------------------------------------
// Scatter: one warp per edge, vector RED atomics
// ---------------------------------------------------------------------------
__device__ __forceinline__ void red_add_v4(float* addr, float a, float b, float c, float d) {
    asm volatile("red.global.add.v4.f32 [%0], {%1, %2, %3, %4};"
                 :: "l"(addr), "f"(a), "f"(b), "f"(c), "f"(d) : "memory");
}

__global__ __launch_bounds__(256) void scatter_kernel(const float* __restrict__ ew,
                                                      const int* __restrict__ esrc,
                                                      const int* __restrict__ edst,
                                                      float* __restrict__ out) {
    const int warp = (blockIdx.x * blockDim.x + threadIdx.x) >> 5;
    const int lane = threadIdx.x & 31;
    if (warp >= N_EDGES) return;

    const int s = esrc[warp];
    const int d = edst[warp];
    const float w = ew[warp];

    const float4* sp = reinterpret_cast<const float4*>(&g_supp[(size_t)s * OUT_SIZE]);
    float* op = &out[(size_t)d * OUT_SIZE];

    const float4 v0 = sp[lane];
    const float4 v1 = sp[32 + lane];

    red_add_v4(op + lane * 4,        v0.x * w, v0.y * w, v0.z * w, v0.w * w);
    red_add_v4(op + (32 + lane) * 4, v1.x * w, v1.y * w, v1.z * w, v1.w * w);
}

// ---------------------------------------------------------------------------
extern "C" void kernel_launch(void* const* d_in, const int* in_sizes, int n_in,
                              void* d_out, int out_size) {
    const float* x      = (const float*)d_in[0];
    const float* weight = (const float*)d_in[1];
    const float* bias   = (const float*)d_in[2];
    const float* ew     = (const float*)d_in[3];
    const int*   esrc   = (const int*)d_in[4];
    const int*   edst   = (const int*)d_in[5];
    float* out = (float*)d_out;

    // 1) W -> bf16 hi/lo split
    prep_w_kernel<<<IN_SIZE * OUT_SIZE / 256, 256>>>(weight);

    // 2) supp = x @ W via HMMA
    dim3 ggrid((N_NODES + 127) / 128, OUT_SIZE / 128);
    gemm_hmma_kernel<<<ggrid, 256>>>(x);

    // 3) out = bias
    bias_init_kernel<<<592, 256>>>(bias, out);

    // 4) out[dst] += supp[src] * w
    scatter_kernel<<<(N_EDGES + 7) / 8, 256>>>(ew, esrc, edst, out);
}

// round 5
// speedup vs baseline: 3.0096x; 1.3850x over previous
#include <cuda_runtime.h>
#include <cuda_bf16.h>
#include <cstdint>

#define N_NODES 100000
#define N_EDGES 800000
#define IN_SIZE 256
#define OUT_SIZE 256
#define NBLK_SCAN ((N_NODES + 1023) / 1024)   // 98

// ---------------------------------------------------------------------------
// Device scratch
// ---------------------------------------------------------------------------
__device__ __align__(128) float g_supp[(size_t)N_NODES * OUT_SIZE];       // x @ W
__device__ __align__(128) __nv_bfloat16 g_w_hi[IN_SIZE * OUT_SIZE];       // W hi [k][n]
__device__ __align__(128) __nv_bfloat16 g_w_lo[IN_SIZE * OUT_SIZE];       // W lo [k][n]

__device__ int   g_deg[N_NODES];
__device__ int   g_loc[N_NODES];        // block-local exclusive scan
__device__ int   g_bsum[128];           // per-block totals -> exclusive scanned
__device__ int   g_off[N_NODES + 1];    // CSR offsets (exclusive)
__device__ int   g_cur[N_NODES];        // fill cursors
__device__ __align__(16) uint2 g_edge[N_EDGES];   // {src, weight bits} sorted by dst

// ---------------------------------------------------------------------------
// Helpers
// ---------------------------------------------------------------------------
__device__ __forceinline__ uint32_t smem_u32(const void* p) {
    uint32_t a;
    asm("{ .reg .u64 t; cvta.to.shared.u64 t, %1; cvt.u32.u64 %0, t; }" : "=r"(a) : "l"(p));
    return a;
}
__device__ __forceinline__ void ldsm_x4(uint32_t* r, uint32_t addr) {
    asm volatile("ldmatrix.sync.aligned.m8n8.x4.shared.b16 {%0,%1,%2,%3}, [%4];"
                 : "=r"(r[0]), "=r"(r[1]), "=r"(r[2]), "=r"(r[3]) : "r"(addr));
}
__device__ __forceinline__ void ldsm_x4_t(uint32_t* r, uint32_t addr) {
    asm volatile("ldmatrix.sync.aligned.m8n8.x4.trans.shared.b16 {%0,%1,%2,%3}, [%4];"
                 : "=r"(r[0]), "=r"(r[1]), "=r"(r[2]), "=r"(r[3]) : "r"(addr));
}
__device__ __forceinline__ void mma_bf16(float* d, const uint32_t* a, const uint32_t* b) {
    asm volatile(
        "mma.sync.aligned.m16n8k16.row.col.f32.bf16.bf16.f32 "
        "{%0,%1,%2,%3}, {%4,%5,%6,%7}, {%8,%9}, {%0,%1,%2,%3};"
        : "+f"(d[0]), "+f"(d[1]), "+f"(d[2]), "+f"(d[3])
        : "r"(a[0]), "r"(a[1]), "r"(a[2]), "r"(a[3]), "r"(b[0]), "r"(b[1]));
}
__device__ __forceinline__ uint32_t bfpack(float x, float y) {
    __nv_bfloat162 t = __floats2bfloat162_rn(x, y);
    return *reinterpret_cast<uint32_t*>(&t);
}
__device__ __forceinline__ void stcs_f4(float* p, float4 v) {
    asm volatile("st.global.cs.v4.f32 [%0], {%1,%2,%3,%4};"
                 :: "l"(p), "f"(v.x), "f"(v.y), "f"(v.z), "f"(v.w) : "memory");
}

// ---------------------------------------------------------------------------
// Prep: W[k][n] fp32 -> bf16 hi/lo split
// ---------------------------------------------------------------------------
__global__ void prep_w_kernel(const float* __restrict__ W) {
    const int idx = blockIdx.x * blockDim.x + threadIdx.x;
    const float v = W[idx];
    const __nv_bfloat16 h = __float2bfloat16_rn(v);
    g_w_hi[idx] = h;
    g_w_lo[idx] = __float2bfloat16_rn(v - __bfloat162float(h));
}

// ---------------------------------------------------------------------------
// GEMM: supp = x @ W, HMMA bf16 3-term split (unchanged from R4)
// ---------------------------------------------------------------------------
#define KC 32
#define LDA 40
#define LDB 136

__global__ __launch_bounds__(256, 1) void gemm_hmma_kernel(const float* __restrict__ X) {
    __shared__ __align__(16) __nv_bfloat16 As_hi[128 * LDA];
    __shared__ __align__(16) __nv_bfloat16 As_lo[128 * LDA];
    __shared__ __align__(16) __nv_bfloat16 Bs_hi[KC * LDB];
    __shared__ __align__(16) __nv_bfloat16 Bs_lo[KC * LDB];

    const int tid = threadIdx.x;
    const int lane = tid & 31;
    const int w = tid >> 5;
    const int wm = w >> 1;
    const int wn = w & 1;
    const int tile_m = blockIdx.x * 128;
    const int tile_n = blockIdx.y * 128;

    const uint32_t as_hi = smem_u32(As_hi);
    const uint32_t as_lo = smem_u32(As_lo);
    const uint32_t bs_hi = smem_u32(Bs_hi);
    const uint32_t bs_lo = smem_u32(Bs_lo);

    float acc[2][8][4];
#pragma unroll
    for (int i = 0; i < 2; i++)
#pragma unroll
        for (int j = 0; j < 8; j++)
#pragma unroll
            for (int q = 0; q < 4; q++) acc[i][j][q] = 0.0f;

    const int a_row = tid >> 3;
    const int a_q = tid & 7;
    const int b_row = tid >> 4;
    const int b_q = tid & 15;
    const int lm_row = lane & 15;
    const int lm_coloff = (lane >> 4) * 8;

    for (int c = 0; c < IN_SIZE / KC; c++) {
        const int k0 = c * KC;

        float4 af[4];
#pragma unroll
        for (int i = 0; i < 4; i++) {
            const int row = a_row + i * 32;
            const int m = tile_m + row;
            af[i] = make_float4(0.f, 0.f, 0.f, 0.f);
            if (m < N_NODES)
                af[i] = *reinterpret_cast<const float4*>(&X[(size_t)m * IN_SIZE + k0 + a_q * 4]);
        }
        float4 bh[2], bl[2];
#pragma unroll
        for (int i = 0; i < 2; i++) {
            const int kr = b_row + i * 16;
            const size_t off = ((size_t)(k0 + kr) * OUT_SIZE + tile_n + b_q * 8) * 2;
            bh[i] = *reinterpret_cast<const float4*>(reinterpret_cast<const char*>(g_w_hi) + off);
            bl[i] = *reinterpret_cast<const float4*>(reinterpret_cast<const char*>(g_w_lo) + off);
        }

        __syncthreads();

#pragma unroll
        for (int i = 0; i < 4; i++) {
            const int row = a_row + i * 32;
            const float4 f = af[i];
            const float hx = __bfloat162float(__float2bfloat16_rn(f.x));
            const float hy = __bfloat162float(__float2bfloat16_rn(f.y));
            const float hz = __bfloat162float(__float2bfloat16_rn(f.z));
            const float hw = __bfloat162float(__float2bfloat16_rn(f.w));
            uint2 hv = make_uint2(bfpack(f.x, f.y), bfpack(f.z, f.w));
            uint2 lv = make_uint2(bfpack(f.x - hx, f.y - hy), bfpack(f.z - hz, f.w - hw));
            *reinterpret_cast<uint2*>(&As_hi[row * LDA + a_q * 4]) = hv;
            *reinterpret_cast<uint2*>(&As_lo[row * LDA + a_q * 4]) = lv;
        }
#pragma unroll
        for (int i = 0; i < 2; i++) {
            const int kr = b_row + i * 16;
            *reinterpret_cast<float4*>(&Bs_hi[kr * LDB + b_q * 8]) = bh[i];
            *reinterpret_cast<float4*>(&Bs_lo[kr * LDB + b_q * 8]) = bl[i];
        }

        __syncthreads();

#pragma unroll
        for (int kk = 0; kk < 2; kk++) {
            const int ks = kk * 16;
            uint32_t a_hi[2][4], a_lo[2][4];
#pragma unroll
            for (int i = 0; i < 2; i++) {
                const uint32_t off =
                    ((uint32_t)(wm * 32 + i * 16 + lm_row) * LDA + ks + lm_coloff) * 2;
                ldsm_x4(a_hi[i], as_hi + off);
                ldsm_x4(a_lo[i], as_lo + off);
            }
            uint32_t b_hi[16], b_lo[16];
#pragma unroll
            for (int jj = 0; jj < 4; jj++) {
                const uint32_t off =
                    ((uint32_t)(ks + lm_row) * LDB + wn * 64 + jj * 16 + lm_coloff) * 2;
                ldsm_x4_t(&b_hi[jj * 4], bs_hi + off);
                ldsm_x4_t(&b_lo[jj * 4], bs_lo + off);
            }
#pragma unroll
            for (int i = 0; i < 2; i++)
#pragma unroll
                for (int j = 0; j < 8; j++) {
                    mma_bf16(acc[i][j], a_hi[i], &b_hi[j * 2]);
                    mma_bf16(acc[i][j], a_hi[i], &b_lo[j * 2]);
                    mma_bf16(acc[i][j], a_lo[i], &b_hi[j * 2]);
                }
        }
    }

    const int er = lane >> 2;
    const int ec = (lane & 3) * 2;
#pragma unroll
    for (int i = 0; i < 2; i++) {
        const int r0 = tile_m + wm * 32 + i * 16 + er;
#pragma unroll
        for (int j = 0; j < 8; j++) {
            const int col = tile_n + wn * 64 + j * 8 + ec;
            if (r0 < N_NODES)
                *reinterpret_cast<float2*>(&g_supp[(size_t)r0 * OUT_SIZE + col]) =
                    make_float2(acc[i][j][0], acc[i][j][1]);
            if (r0 + 8 < N_NODES)
                *reinterpret_cast<float2*>(&g_supp[(size_t)(r0 + 8) * OUT_SIZE + col]) =
                    make_float2(acc[i][j][2], acc[i][j][3]);
        }
    }
}

// ---------------------------------------------------------------------------
// CSR build: zero -> histogram -> scan(3) -> fill
// ---------------------------------------------------------------------------
__global__ void zero_deg_kernel() {
    const int i = blockIdx.x * blockDim.x + threadIdx.x;
    if (i < N_NODES) g_deg[i] = 0;
}

__global__ void hist_kernel(const int* __restrict__ edst) {
    const int e = blockIdx.x * blockDim.x + threadIdx.x;
    if (e < N_EDGES) atomicAdd(&g_deg[edst[e]], 1);
}

__global__ __launch_bounds__(1024) void scan1_kernel() {
    __shared__ int s[1024];
    const int tid = threadIdx.x;
    const int i = blockIdx.x * 1024 + tid;
    const int v = (i < N_NODES) ? g_deg[i] : 0;
    s[tid] = v;
    __syncthreads();
#pragma unroll
    for (int d = 1; d < 1024; d <<= 1) {
        int t = (tid >= d) ? s[tid - d] : 0;
        __syncthreads();
        s[tid] += t;
        __syncthreads();
    }
    if (i < N_NODES) g_loc[i] = s[tid] - v;     // exclusive within block
    if (tid == 1023) g_bsum[blockIdx.x] = s[1023];
}

__global__ __launch_bounds__(128) void scan2_kernel() {
    __shared__ int s[128];
    const int tid = threadIdx.x;
    const int v = (tid < NBLK_SCAN) ? g_bsum[tid] : 0;
    s[tid] = v;
    __syncthreads();
#pragma unroll
    for (int d = 1; d < 128; d <<= 1) {
        int t = (tid >= d) ? s[tid - d] : 0;
        __syncthreads();
        s[tid] += t;
        __syncthreads();
    }
    g_bsum[tid] = s[tid] - v;                    // exclusive block offsets
}

__global__ void scan3_kernel() {
    const int i = blockIdx.x * blockDim.x + threadIdx.x;
    if (i < N_NODES) {
        const int off = g_loc[i] + g_bsum[i >> 10];
        g_off[i] = off;
        g_cur[i] = off;
    }
    if (i == 0) g_off[N_NODES] = N_EDGES;
}

__global__ void fill_kernel(const float* __restrict__ ew,
                            const int* __restrict__ esrc,
                            const int* __restrict__ edst) {
    const int e = blockIdx.x * blockDim.x + threadIdx.x;
    if (e < N_EDGES) {
        const int p = atomicAdd(&g_cur[edst[e]], 1);
        g_edge[p] = make_uint2((uint32_t)esrc[e], __float_as_uint(ew[e]));
    }
}

// ---------------------------------------------------------------------------
// Aggregate: one warp per destination node. out[d] = sum supp[src]*w + bias
// ---------------------------------------------------------------------------
__global__ __launch_bounds__(256) void aggregate_kernel(const float* __restrict__ bias,
                                                        float* __restrict__ out) {
    const int d = (blockIdx.x * blockDim.x + threadIdx.x) >> 5;
    const int lane = threadIdx.x & 31;
    if (d >= N_NODES) return;

    const int beg = g_off[d];
    const int end = g_off[d + 1];

    float4 acc0 = make_float4(0.f, 0.f, 0.f, 0.f);
    float4 acc1 = make_float4(0.f, 0.f, 0.f, 0.f);

    int p = beg;
    // 2-edge unrolled for MLP
    for (; p + 1 < end; p += 2) {
        const uint2 e0 = g_edge[p];
        const uint2 e1 = g_edge[p + 1];
        const float w0 = __uint_as_float(e0.y);
        const float w1 = __uint_as_float(e1.y);
        const float4* s0 = reinterpret_cast<const float4*>(&g_supp[(size_t)e0.x * OUT_SIZE]);
        const float4* s1 = reinterpret_cast<const float4*>(&g_supp[(size_t)e1.x * OUT_SIZE]);
        const float4 a = s0[lane];
        const float4 b = s0[32 + lane];
        const float4 c = s1[lane];
        const float4 dd = s1[32 + lane];
        acc0.x = fmaf(a.x, w0, acc0.x); acc0.y = fmaf(a.y, w0, acc0.y);
        acc0.z = fmaf(a.z, w0, acc0.z); acc0.w = fmaf(a.w, w0, acc0.w);
        acc1.x = fmaf(b.x, w0, acc1.x); acc1.y = fmaf(b.y, w0, acc1.y);
        acc1.z = fmaf(b.z, w0, acc1.z); acc1.w = fmaf(b.w, w0, acc1.w);
        acc0.x = fmaf(c.x, w1, acc0.x); acc0.y = fmaf(c.y, w1, acc0.y);
        acc0.z = fmaf(c.z, w1, acc0.z); acc0.w = fmaf(c.w, w1, acc0.w);
        acc1.x = fmaf(dd.x, w1, acc1.x); acc1.y = fmaf(dd.y, w1, acc1.y);
        acc1.z = fmaf(dd.z, w1, acc1.z); acc1.w = fmaf(dd.w, w1, acc1.w);
    }
    if (p < end) {
        const uint2 e0 = g_edge[p];
        const float w0 = __uint_as_float(e0.y);
        const float4* s0 = reinterpret_cast<const float4*>(&g_supp[(size_t)e0.x * OUT_SIZE]);
        const float4 a = s0[lane];
        const float4 b = s0[32 + lane];
        acc0.x = fmaf(a.x, w0, acc0.x); acc0.y = fmaf(a.y, w0, acc0.y);
        acc0.z = fmaf(a.z, w0, acc0.z); acc0.w = fmaf(a.w, w0, acc0.w);
        acc1.x = fmaf(b.x, w0, acc1.x); acc1.y = fmaf(b.y, w0, acc1.y);
        acc1.z = fmaf(b.z, w0, acc1.z); acc1.w = fmaf(b.w, w0, acc1.w);
    }

    // + bias
    const float4 b0 = reinterpret_cast<const float4*>(bias)[lane];
    const float4 b1 = reinterpret_cast<const float4*>(bias)[32 + lane];
    acc0.x += b0.x; acc0.y += b0.y; acc0.z += b0.z; acc0.w += b0.w;
    acc1.x += b1.x; acc1.y += b1.y; acc1.z += b1.z; acc1.w += b1.w;

    float* op = &out[(size_t)d * OUT_SIZE];
    stcs_f4(op + lane * 4, acc0);
    stcs_f4(op + (32 + lane) * 4, acc1);
}

// ---------------------------------------------------------------------------
extern "C" void kernel_launch(void* const* d_in, const int* in_sizes, int n_in,
                              void* d_out, int out_size) {
    const float* x      = (const float*)d_in[0];
    const float* weight = (const float*)d_in[1];
    const float* bias   = (const float*)d_in[2];
    const float* ew     = (const float*)d_in[3];
    const int*   esrc   = (const int*)d_in[4];
    const int*   edst   = (const int*)d_in[5];
    float* out = (float*)d_out;

    // 1) W -> bf16 hi/lo split
    prep_w_kernel<<<IN_SIZE * OUT_SIZE / 256, 256>>>(weight);

    // 2) supp = x @ W via HMMA
    dim3 ggrid((N_NODES + 127) / 128, OUT_SIZE / 128);
    gemm_hmma_kernel<<<ggrid, 256>>>(x);

    // 3) CSR build (overlaps GEMM on the same stream order; cheap)
    zero_deg_kernel<<<(N_NODES + 255) / 256, 256>>>();
    hist_kernel<<<(N_EDGES + 255) / 256, 256>>>(edst);
    scan1_kernel<<<NBLK_SCAN, 1024>>>();
    scan2_kernel<<<1, 128>>>();
    scan3_kernel<<<(N_NODES + 255) / 256, 256>>>();
    fill_kernel<<<(N_EDGES + 255) / 256, 256>>>(ew, esrc, edst);

    // 4) out[d] = sum_{e: dst=d} supp[src_e] * w_e + bias
    aggregate_kernel<<<(N_NODES * 32 + 255) / 256, 256>>>(bias, out);
}

// round 6
// speedup vs baseline: 3.4774x; 1.1554x over previous
#include <cuda_runtime.h>
#include <cuda_bf16.h>
#include <cstdint>

#define N_NODES 100000
#define N_EDGES 800000
#define IN_SIZE 256
#define OUT_SIZE 256
#define NBLK_SCAN ((N_NODES + 1023) / 1024)   // 98

// ---------------------------------------------------------------------------
// Device scratch
// ---------------------------------------------------------------------------
__device__ __align__(128) float g_supp[(size_t)N_NODES * OUT_SIZE];       // x @ W
__device__ __align__(128) __nv_bfloat16 g_w_hi[IN_SIZE * OUT_SIZE];       // W hi [k][n]
__device__ __align__(128) __nv_bfloat16 g_w_lo[IN_SIZE * OUT_SIZE];       // W lo [k][n]

__device__ int   g_deg[N_NODES];
__device__ int   g_loc[N_NODES];
__device__ int   g_bsum[128];
__device__ int   g_off[N_NODES + 1];
__device__ int   g_cur[N_NODES];
__device__ __align__(16) uint2 g_edge[N_EDGES];   // {src, weight bits} grouped by dst

// ---------------------------------------------------------------------------
// Helpers
// ---------------------------------------------------------------------------
__device__ __forceinline__ uint32_t smem_u32(const void* p) {
    uint32_t a;
    asm("{ .reg .u64 t; cvta.to.shared.u64 t, %1; cvt.u32.u64 %0, t; }" : "=r"(a) : "l"(p));
    return a;
}
__device__ __forceinline__ void ldsm_x4(uint32_t* r, uint32_t addr) {
    asm volatile("ldmatrix.sync.aligned.m8n8.x4.shared.b16 {%0,%1,%2,%3}, [%4];"
                 : "=r"(r[0]), "=r"(r[1]), "=r"(r[2]), "=r"(r[3]) : "r"(addr));
}
__device__ __forceinline__ void ldsm_x4_t(uint32_t* r, uint32_t addr) {
    asm volatile("ldmatrix.sync.aligned.m8n8.x4.trans.shared.b16 {%0,%1,%2,%3}, [%4];"
                 : "=r"(r[0]), "=r"(r[1]), "=r"(r[2]), "=r"(r[3]) : "r"(addr));
}
__device__ __forceinline__ void mma_bf16(float* d, const uint32_t* a, const uint32_t* b) {
    asm volatile(
        "mma.sync.aligned.m16n8k16.row.col.f32.bf16.bf16.f32 "
        "{%0,%1,%2,%3}, {%4,%5,%6,%7}, {%8,%9}, {%0,%1,%2,%3};"
        : "+f"(d[0]), "+f"(d[1]), "+f"(d[2]), "+f"(d[3])
        : "r"(a[0]), "r"(a[1]), "r"(a[2]), "r"(a[3]), "r"(b[0]), "r"(b[1]));
}
__device__ __forceinline__ uint32_t bfpack(float x, float y) {
    __nv_bfloat162 t = __floats2bfloat162_rn(x, y);
    return *reinterpret_cast<uint32_t*>(&t);
}
__device__ __forceinline__ void stcs_f4(float* p, float4 v) {
    asm volatile("st.global.cs.v4.f32 [%0], {%1,%2,%3,%4};"
                 :: "l"(p), "f"(v.x), "f"(v.y), "f"(v.z), "f"(v.w) : "memory");
}
__device__ __forceinline__ void cp16(uint32_t dst, const void* src) {
    asm volatile("cp.async.ca.shared.global [%0], [%1], 16;" :: "r"(dst), "l"(src));
}
#define CP_COMMIT() asm volatile("cp.async.commit_group;" ::: "memory")
#define CP_WAIT0()  asm volatile("cp.async.wait_group 0;" ::: "memory")

// ---------------------------------------------------------------------------
// Prep: W[k][n] fp32 -> bf16 hi/lo split
// ---------------------------------------------------------------------------
__global__ void prep_w_kernel(const float* __restrict__ W) {
    const int idx = blockIdx.x * blockDim.x + threadIdx.x;
    const float v = W[idx];
    const __nv_bfloat16 h = __float2bfloat16_rn(v);
    g_w_hi[idx] = h;
    g_w_lo[idx] = __float2bfloat16_rn(v - __bfloat162float(h));
}

// ---------------------------------------------------------------------------
// GEMM: supp = x @ W, HMMA bf16 3-term split, double-buffered pipeline.
// CTA 128x128, warps 4(M)x2(N), KC=32, one __syncthreads per chunk.
// ---------------------------------------------------------------------------
#define KC 32
#define LDA 40    // bf16 elems per A smem row (32 + 8 pad) = 80 B
#define LDB 136   // bf16 elems per B smem row (128 + 8 pad) = 272 B

// per-buffer byte offsets within one stage
#define OFF_AH 0
#define OFF_AL 10240
#define OFF_BH 20480
#define OFF_BL 29184
#define STAGE  37888
#define GEMM_SMEM (2 * STAGE)   // 75776

__global__ __launch_bounds__(256, 1) void gemm_hmma_kernel(const float* __restrict__ X) {
    extern __shared__ __align__(16) char smem[];
    const uint32_t sb = smem_u32(smem);

    const int tid = threadIdx.x;
    const int lane = tid & 31;
    const int w = tid >> 5;
    const int wm = w >> 1;
    const int wn = w & 1;
    const int tile_m = blockIdx.x * 128;
    const int tile_n = blockIdx.y * 128;

    float acc[2][8][4];
#pragma unroll
    for (int i = 0; i < 2; i++)
#pragma unroll
        for (int j = 0; j < 8; j++)
#pragma unroll
            for (int q = 0; q < 4; q++) acc[i][j][q] = 0.0f;

    // A LDG mapping: rows a_row + i*32, float4 slot a_q (8 slots * 4 floats = 32 k)
    const int a_row = tid >> 3;
    const int a_q = tid & 7;
    // B cp.async mapping: row = tid>>3 (0..31), two 16B segs per row
    const int b_row = tid >> 3;
    const int b_seg = tid & 7;
    // ldmatrix lane addressing
    const int lm_row = lane & 15;
    const int lm_coloff = (lane >> 4) * 8;

    const bool a_ok0 = (tile_m + a_row) < N_NODES;

    // ---- prologue: LDG A(0), cp.async B(0) -> buf 0
    float4 af[4];
#pragma unroll
    for (int i = 0; i < 4; i++) {
        const int m = tile_m + a_row + i * 32;
        af[i] = make_float4(0.f, 0.f, 0.f, 0.f);
        if (m < N_NODES)
            af[i] = *reinterpret_cast<const float4*>(&X[(size_t)m * IN_SIZE + a_q * 4]);
    }
    {
        const uint32_t d0 = sb + OFF_BH + b_row * 272;
        const uint32_t d1 = sb + OFF_BL + b_row * 272;
        const size_t s0 = (size_t)b_row * OUT_SIZE + tile_n;   // k row b_row of chunk 0
        cp16(d0 + b_seg * 16,        &g_w_hi[s0 + b_seg * 8]);
        cp16(d0 + (b_seg + 8) * 16,  &g_w_hi[s0 + (b_seg + 8) * 8]);
        cp16(d1 + b_seg * 16,        &g_w_lo[s0 + b_seg * 8]);
        cp16(d1 + (b_seg + 8) * 16,  &g_w_lo[s0 + (b_seg + 8) * 8]);
        CP_COMMIT();
    }

    for (int c = 0; c < IN_SIZE / KC; c++) {
        const int b = c & 1;
        const uint32_t buf = sb + b * STAGE;
        char* bufp = smem + b * STAGE;

        // ---- convert + store A(c) into buf
#pragma unroll
        for (int i = 0; i < 4; i++) {
            const int row = a_row + i * 32;
            const float4 f = af[i];
            const float hx = __bfloat162float(__float2bfloat16_rn(f.x));
            const float hy = __bfloat162float(__float2bfloat16_rn(f.y));
            const float hz = __bfloat162float(__float2bfloat16_rn(f.z));
            const float hw = __bfloat162float(__float2bfloat16_rn(f.w));
            uint2 hv = make_uint2(bfpack(f.x, f.y), bfpack(f.z, f.w));
            uint2 lv = make_uint2(bfpack(f.x - hx, f.y - hy), bfpack(f.z - hz, f.w - hw));
            *reinterpret_cast<uint2*>(bufp + OFF_AH + (row * LDA + a_q * 4) * 2) = hv;
            *reinterpret_cast<uint2*>(bufp + OFF_AL + (row * LDA + a_q * 4) * 2) = lv;
        }

        CP_WAIT0();          // B(c) resident
        __syncthreads();     // all stores + cp.asyncs of this buf visible

        // ---- issue next chunk's global traffic (overlaps compute below)
        if (c + 1 < IN_SIZE / KC) {
            const int k0n = (c + 1) * KC;
#pragma unroll
            for (int i = 0; i < 4; i++) {
                const int m = tile_m + a_row + i * 32;
                af[i] = make_float4(0.f, 0.f, 0.f, 0.f);
                if (a_ok0 ? (m < N_NODES) : (m < N_NODES))   // keep simple predicate
                    af[i] = *reinterpret_cast<const float4*>(&X[(size_t)m * IN_SIZE + k0n + a_q * 4]);
            }
            const uint32_t nbuf = sb + (b ^ 1) * STAGE;
            const uint32_t d0 = nbuf + OFF_BH + b_row * 272;
            const uint32_t d1 = nbuf + OFF_BL + b_row * 272;
            const size_t s0 = (size_t)(k0n + b_row) * OUT_SIZE + tile_n;
            cp16(d0 + b_seg * 16,       &g_w_hi[s0 + b_seg * 8]);
            cp16(d0 + (b_seg + 8) * 16, &g_w_hi[s0 + (b_seg + 8) * 8]);
            cp16(d1 + b_seg * 16,       &g_w_lo[s0 + b_seg * 8]);
            cp16(d1 + (b_seg + 8) * 16, &g_w_lo[s0 + (b_seg + 8) * 8]);
            CP_COMMIT();
        }

        // ---- compute chunk c from buf
        const uint32_t as_hi = buf + OFF_AH;
        const uint32_t as_lo = buf + OFF_AL;
        const uint32_t bs_hi = buf + OFF_BH;
        const uint32_t bs_lo = buf + OFF_BL;

#pragma unroll
        for (int kk = 0; kk < 2; kk++) {
            const int ks = kk * 16;
            uint32_t a_hi[2][4], a_lo[2][4];
#pragma unroll
            for (int i = 0; i < 2; i++) {
                const uint32_t off =
                    ((uint32_t)(wm * 32 + i * 16 + lm_row) * LDA + ks + lm_coloff) * 2;
                ldsm_x4(a_hi[i], as_hi + off);
                ldsm_x4(a_lo[i], as_lo + off);
            }
            uint32_t b_hi[16], b_lo[16];
#pragma unroll
            for (int jj = 0; jj < 4; jj++) {
                const uint32_t off =
                    ((uint32_t)(ks + lm_row) * LDB + wn * 64 + jj * 16 + lm_coloff) * 2;
                ldsm_x4_t(&b_hi[jj * 4], bs_hi + off);
                ldsm_x4_t(&b_lo[jj * 4], bs_lo + off);
            }
#pragma unroll
            for (int i = 0; i < 2; i++)
#pragma unroll
                for (int j = 0; j < 8; j++) {
                    mma_bf16(acc[i][j], a_hi[i], &b_hi[j * 2]);
                    mma_bf16(acc[i][j], a_hi[i], &b_lo[j * 2]);
                    mma_bf16(acc[i][j], a_lo[i], &b_hi[j * 2]);
                }
        }
    }

    // ---- epilogue
    const int er = lane >> 2;
    const int ec = (lane & 3) * 2;
#pragma unroll
    for (int i = 0; i < 2; i++) {
        const int r0 = tile_m + wm * 32 + i * 16 + er;
#pragma unroll
        for (int j = 0; j < 8; j++) {
            const int col = tile_n + wn * 64 + j * 8 + ec;
            if (r0 < N_NODES)
                *reinterpret_cast<float2*>(&g_supp[(size_t)r0 * OUT_SIZE + col]) =
                    make_float2(acc[i][j][0], acc[i][j][1]);
            if (r0 + 8 < N_NODES)
                *reinterpret_cast<float2*>(&g_supp[(size_t)(r0 + 8) * OUT_SIZE + col]) =
                    make_float2(acc[i][j][2], acc[i][j][3]);
        }
    }
}

// ---------------------------------------------------------------------------
// CSR build: zero -> histogram -> scan(3) -> fill
// ---------------------------------------------------------------------------
__global__ void zero_deg_kernel() {
    const int i = blockIdx.x * blockDim.x + threadIdx.x;
    if (i < N_NODES) g_deg[i] = 0;
}

__global__ void hist_kernel(const int* __restrict__ edst) {
    const int e = blockIdx.x * blockDim.x + threadIdx.x;
    if (e < N_EDGES) atomicAdd(&g_deg[edst[e]], 1);
}

__global__ __launch_bounds__(1024) void scan1_kernel() {
    __shared__ int s[1024];
    const int tid = threadIdx.x;
    const int i = blockIdx.x * 1024 + tid;
    const int v = (i < N_NODES) ? g_deg[i] : 0;
    s[tid] = v;
    __syncthreads();
#pragma unroll
    for (int d = 1; d < 1024; d <<= 1) {
        int t = (tid >= d) ? s[tid - d] : 0;
        __syncthreads();
        s[tid] += t;
        __syncthreads();
    }
    if (i < N_NODES) g_loc[i] = s[tid] - v;
    if (tid == 1023) g_bsum[blockIdx.x] = s[1023];
}

__global__ __launch_bounds__(128) void scan2_kernel() {
    __shared__ int s[128];
    const int tid = threadIdx.x;
    const int v = (tid < NBLK_SCAN) ? g_bsum[tid] : 0;
    s[tid] = v;
    __syncthreads();
#pragma unroll
    for (int d = 1; d < 128; d <<= 1) {
        int t = (tid >= d) ? s[tid - d] : 0;
        __syncthreads();
        s[tid] += t;
        __syncthreads();
    }
    g_bsum[tid] = s[tid] - v;
}

__global__ void scan3_kernel() {
    const int i = blockIdx.x * blockDim.x + threadIdx.x;
    if (i < N_NODES) {
        const int off = g_loc[i] + g_bsum[i >> 10];
        g_off[i] = off;
        g_cur[i] = off;
    }
    if (i == 0) g_off[N_NODES] = N_EDGES;
}

__global__ void fill_kernel(const float* __restrict__ ew,
                            const int* __restrict__ esrc,
                            const int* __restrict__ edst) {
    const int e = blockIdx.x * blockDim.x + threadIdx.x;
    if (e < N_EDGES) {
        const int p = atomicAdd(&g_cur[edst[e]], 1);
        g_edge[p] = make_uint2((uint32_t)esrc[e], __float_as_uint(ew[e]));
    }
}

// ---------------------------------------------------------------------------
// Aggregate: one warp per destination node. out[d] = sum supp[src]*w + bias
// ---------------------------------------------------------------------------
__global__ __launch_bounds__(256) void aggregate_kernel(const float* __restrict__ bias,
                                                        float* __restrict__ out) {
    const int d = (blockIdx.x * blockDim.x + threadIdx.x) >> 5;
    const int lane = threadIdx.x & 31;
    if (d >= N_NODES) return;

    const int beg = g_off[d];
    const int end = g_off[d + 1];

    float4 acc0 = make_float4(0.f, 0.f, 0.f, 0.f);
    float4 acc1 = make_float4(0.f, 0.f, 0.f, 0.f);

    int p = beg;
    for (; p + 1 < end; p += 2) {
        const uint2 e0 = g_edge[p];
        const uint2 e1 = g_edge[p + 1];
        const float w0 = __uint_as_float(e0.y);
        const float w1 = __uint_as_float(e1.y);
        const float4* s0 = reinterpret_cast<const float4*>(&g_supp[(size_t)e0.x * OUT_SIZE]);
        const float4* s1 = reinterpret_cast<const float4*>(&g_supp[(size_t)e1.x * OUT_SIZE]);
        const float4 a = s0[lane];
        const float4 b = s0[32 + lane];
        const float4 c = s1[lane];
        const float4 dd = s1[32 + lane];
        acc0.x = fmaf(a.x, w0, acc0.x); acc0.y = fmaf(a.y, w0, acc0.y);
        acc0.z = fmaf(a.z, w0, acc0.z); acc0.w = fmaf(a.w, w0, acc0.w);
        acc1.x = fmaf(b.x, w0, acc1.x); acc1.y = fmaf(b.y, w0, acc1.y);
        acc1.z = fmaf(b.z, w0, acc1.z); acc1.w = fmaf(b.w, w0, acc1.w);
        acc0.x = fmaf(c.x, w1, acc0.x); acc0.y = fmaf(c.y, w1, acc0.y);
        acc0.z = fmaf(c.z, w1, acc0.z); acc0.w = fmaf(c.w, w1, acc0.w);
        acc1.x = fmaf(dd.x, w1, acc1.x); acc1.y = fmaf(dd.y, w1, acc1.y);
        acc1.z = fmaf(dd.z, w1, acc1.z); acc1.w = fmaf(dd.w, w1, acc1.w);
    }
    if (p < end) {
        const uint2 e0 = g_edge[p];
        const float w0 = __uint_as_float(e0.y);
        const float4* s0 = reinterpret_cast<const float4*>(&g_supp[(size_t)e0.x * OUT_SIZE]);
        const float4 a = s0[lane];
        const float4 b = s0[32 + lane];
        acc0.x = fmaf(a.x, w0, acc0.x); acc0.y = fmaf(a.y, w0, acc0.y);
        acc0.z = fmaf(a.z, w0, acc0.z); acc0.w = fmaf(a.w, w0, acc0.w);
        acc1.x = fmaf(b.x, w0, acc1.x); acc1.y = fmaf(b.y, w0, acc1.y);
        acc1.z = fmaf(b.z, w0, acc1.z); acc1.w = fmaf(b.w, w0, acc1.w);
    }

    const float4 b0 = reinterpret_cast<const float4*>(bias)[lane];
    const float4 b1 = reinterpret_cast<const float4*>(bias)[32 + lane];
    acc0.x += b0.x; acc0.y += b0.y; acc0.z += b0.z; acc0.w += b0.w;
    acc1.x += b1.x; acc1.y += b1.y; acc1.z += b1.z; acc1.w += b1.w;

    float* op = &out[(size_t)d * OUT_SIZE];
    stcs_f4(op + lane * 4, acc0);
    stcs_f4(op + (32 + lane) * 4, acc1);
}

// ---------------------------------------------------------------------------
extern "C" void kernel_launch(void* const* d_in, const int* in_sizes, int n_in,
                              void* d_out, int out_size) {
    const float* x      = (const float*)d_in[0];
    const float* weight = (const float*)d_in[1];
    const float* bias   = (const float*)d_in[2];
    const float* ew     = (const float*)d_in[3];
    const int*   esrc   = (const int*)d_in[4];
    const int*   edst   = (const int*)d_in[5];
    float* out = (float*)d_out;

    static bool attr_done = false;
    if (!attr_done) {
        cudaFuncSetAttribute(gemm_hmma_kernel, cudaFuncAttributeMaxDynamicSharedMemorySize,
                             GEMM_SMEM);
        attr_done = true;
    }

    // 1) W -> bf16 hi/lo split
    prep_w_kernel<<<IN_SIZE * OUT_SIZE / 256, 256>>>(weight);

    // 2) supp = x @ W via pipelined HMMA
    dim3 ggrid((N_NODES + 127) / 128, OUT_SIZE / 128);
    gemm_hmma_kernel<<<ggrid, 256, GEMM_SMEM>>>(x);

    // 3) CSR build
    zero_deg_kernel<<<(N_NODES + 255) / 256, 256>>>();
    hist_kernel<<<(N_EDGES + 255) / 256, 256>>>(edst);
    scan1_kernel<<<NBLK_SCAN, 1024>>>();
    scan2_kernel<<<1, 128>>>();
    scan3_kernel<<<(N_NODES + 255) / 256, 256>>>();
    fill_kernel<<<(N_EDGES + 255) / 256, 256>>>(ew, esrc, edst);

    // 4) out[d] = sum supp[src]*w + bias
    aggregate_kernel<<<(N_NODES * 32 + 255) / 256, 256>>>(bias, out);
}

// round 8
// speedup vs baseline: 3.7295x; 1.0725x over previous
#include <cuda_runtime.h>
#include <cuda_bf16.h>
#include <cstdint>

#define N_NODES 100000
#define N_EDGES 800000
#define IN_SIZE 256
#define OUT_SIZE 256
#define NBLK_SCAN ((N_NODES + 1023) / 1024)   // 98

// ---------------------------------------------------------------------------
// Device scratch
// ---------------------------------------------------------------------------
__device__ __align__(128) float g_supp[(size_t)N_NODES * OUT_SIZE];       // x @ W
__device__ __align__(128) __nv_bfloat16 g_w_hi[IN_SIZE * OUT_SIZE];       // W hi [k][n]
__device__ __align__(128) __nv_bfloat16 g_w_lo[IN_SIZE * OUT_SIZE];       // W lo [k][n]

__device__ int   g_deg[N_NODES];
__device__ int   g_loc[N_NODES];
__device__ int   g_bsum[128];
__device__ int   g_off[N_NODES + 1];
__device__ int   g_cur[N_NODES];
__device__ __align__(16) uint2 g_edge[N_EDGES];   // {src, weight bits} grouped by dst

// ---------------------------------------------------------------------------
// Helpers
// ---------------------------------------------------------------------------
__device__ __forceinline__ uint32_t smem_u32(const void* p) {
    uint32_t a;
    asm("{ .reg .u64 t; cvta.to.shared.u64 t, %1; cvt.u32.u64 %0, t; }" : "=r"(a) : "l"(p));
    return a;
}
__device__ __forceinline__ void ldsm_x4(uint32_t* r, uint32_t addr) {
    asm volatile("ldmatrix.sync.aligned.m8n8.x4.shared.b16 {%0,%1,%2,%3}, [%4];"
                 : "=r"(r[0]), "=r"(r[1]), "=r"(r[2]), "=r"(r[3]) : "r"(addr));
}
__device__ __forceinline__ void ldsm_x4_t(uint32_t* r, uint32_t addr) {
    asm volatile("ldmatrix.sync.aligned.m8n8.x4.trans.shared.b16 {%0,%1,%2,%3}, [%4];"
                 : "=r"(r[0]), "=r"(r[1]), "=r"(r[2]), "=r"(r[3]) : "r"(addr));
}
__device__ __forceinline__ void mma_bf16(float* d, const uint32_t* a, const uint32_t* b) {
    asm volatile(
        "mma.sync.aligned.m16n8k16.row.col.f32.bf16.bf16.f32 "
        "{%0,%1,%2,%3}, {%4,%5,%6,%7}, {%8,%9}, {%0,%1,%2,%3};"
        : "+f"(d[0]), "+f"(d[1]), "+f"(d[2]), "+f"(d[3])
        : "r"(a[0]), "r"(a[1]), "r"(a[2]), "r"(a[3]), "r"(b[0]), "r"(b[1]));
}
__device__ __forceinline__ uint32_t bfpack(float x, float y) {
    __nv_bfloat162 t = __floats2bfloat162_rn(x, y);
    return *reinterpret_cast<uint32_t*>(&t);
}
__device__ __forceinline__ void stcs_f4(float* p, float4 v) {
    asm volatile("st.global.cs.v4.f32 [%0], {%1,%2,%3,%4};"
                 :: "l"(p), "f"(v.x), "f"(v.y), "f"(v.z), "f"(v.w) : "memory");
}
__device__ __forceinline__ void cp16(uint32_t dst, const void* src) {
    asm volatile("cp.async.ca.shared.global [%0], [%1], 16;" :: "r"(dst), "l"(src));
}
#define CP_COMMIT() asm volatile("cp.async.commit_group;" ::: "memory")
#define CP_WAIT0()  asm volatile("cp.async.wait_group 0;" ::: "memory")

// ---------------------------------------------------------------------------
// Prep: W[k][n] fp32 -> bf16 hi/lo split
// ---------------------------------------------------------------------------
__global__ void prep_w_kernel(const float* __restrict__ W) {
    const int idx = blockIdx.x * blockDim.x + threadIdx.x;
    const float v = W[idx];
    const __nv_bfloat16 h = __float2bfloat16_rn(v);
    g_w_hi[idx] = h;
    g_w_lo[idx] = __float2bfloat16_rn(v - __bfloat162float(h));
}

// ---------------------------------------------------------------------------
// GEMM: supp = x @ W, HMMA bf16 3-term split, double-buffered pipeline.
// CTA 128(M)x64(N), warps 4(M)x2(N) -> warp tile 32x32. 2 CTAs/SM.
// ---------------------------------------------------------------------------
#define KC 32
#define LDA 40    // bf16 elems per A smem row (32 + 8 pad) = 80 B
#define LDB 72    // bf16 elems per B smem row (64 + 8 pad) = 144 B

#define OFF_AH 0
#define OFF_AL 10240
#define OFF_BH 20480
#define OFF_BL 25088
#define STAGE  29696
#define GEMM_SMEM (2 * STAGE)   // 59392

__global__ __launch_bounds__(256, 2) void gemm_hmma_kernel(const float* __restrict__ X) {
    extern __shared__ __align__(16) char smem[];
    const uint32_t sb = smem_u32(smem);

    const int tid = threadIdx.x;
    const int lane = tid & 31;
    const int w = tid >> 5;
    const int wm = w >> 1;        // 0..3  (M)
    const int wn = w & 1;         // 0..1  (N)
    const int tile_n = blockIdx.x * 64;    // fast dim -> A reuse in L2
    const int tile_m = blockIdx.y * 128;

    float acc[2][4][4];
#pragma unroll
    for (int i = 0; i < 2; i++)
#pragma unroll
        for (int j = 0; j < 4; j++)
#pragma unroll
            for (int q = 0; q < 4; q++) acc[i][j][q] = 0.0f;

    // A LDG mapping: 128 rows x 8 float4 slots, 4 per thread
    const int a_row = tid >> 3;
    const int a_q = tid & 7;
    // B cp.async mapping: 32 rows x 8 segs of 16B (64 bf16 = 128B per row).
    // Each thread copies hi seg b_seg AND lo seg b_seg of its row.
    const int b_row = tid >> 3;        // 0..31
    const int b_seg = tid & 7;         // 0..7
    const int lm_row = lane & 15;
    const int lm_coloff = (lane >> 4) * 8;

    // ---- prologue: LDG A(0), cp.async B(0) -> buf 0
    float4 af[4];
#pragma unroll
    for (int i = 0; i < 4; i++) {
        const int m = tile_m + a_row + i * 32;
        af[i] = make_float4(0.f, 0.f, 0.f, 0.f);
        if (m < N_NODES)
            af[i] = *reinterpret_cast<const float4*>(&X[(size_t)m * IN_SIZE + a_q * 4]);
    }
    {
        const size_t s0 = (size_t)b_row * OUT_SIZE + tile_n + b_seg * 8;
        cp16(sb + OFF_BH + b_row * 144 + b_seg * 16, &g_w_hi[s0]);
        cp16(sb + OFF_BL + b_row * 144 + b_seg * 16, &g_w_lo[s0]);
        CP_COMMIT();
    }

    for (int c = 0; c < IN_SIZE / KC; c++) {
        const int b = c & 1;
        const uint32_t buf = sb + b * STAGE;
        char* bufp = smem + b * STAGE;

        // ---- convert + store A(c)
#pragma unroll
        for (int i = 0; i < 4; i++) {
            const int row = a_row + i * 32;
            const float4 f = af[i];
            const float hx = __bfloat162float(__float2bfloat16_rn(f.x));
            const float hy = __bfloat162float(__float2bfloat16_rn(f.y));
            const float hz = __bfloat162float(__float2bfloat16_rn(f.z));
            const float hw = __bfloat162float(__float2bfloat16_rn(f.w));
            uint2 hv = make_uint2(bfpack(f.x, f.y), bfpack(f.z, f.w));
            uint2 lv = make_uint2(bfpack(f.x - hx, f.y - hy), bfpack(f.z - hz, f.w - hw));
            *reinterpret_cast<uint2*>(bufp + OFF_AH + (row * LDA + a_q * 4) * 2) = hv;
            *reinterpret_cast<uint2*>(bufp + OFF_AL + (row * LDA + a_q * 4) * 2) = lv;
        }

        CP_WAIT0();
        __syncthreads();

        // ---- prefetch next chunk (overlaps compute)
        if (c + 1 < IN_SIZE / KC) {
            const int k0n = (c + 1) * KC;
#pragma unroll
            for (int i = 0; i < 4; i++) {
                const int m = tile_m + a_row + i * 32;
                af[i] = make_float4(0.f, 0.f, 0.f, 0.f);
                if (m < N_NODES)
                    af[i] = *reinterpret_cast<const float4*>(&X[(size_t)m * IN_SIZE + k0n + a_q * 4]);
            }
            const uint32_t nbuf = sb + (b ^ 1) * STAGE;
            const size_t s0 = (size_t)(k0n + b_row) * OUT_SIZE + tile_n + b_seg * 8;
            cp16(nbuf + OFF_BH + b_row * 144 + b_seg * 16, &g_w_hi[s0]);
            cp16(nbuf + OFF_BL + b_row * 144 + b_seg * 16, &g_w_lo[s0]);
            CP_COMMIT();
        }

        // ---- compute chunk c
        const uint32_t as_hi = buf + OFF_AH;
        const uint32_t as_lo = buf + OFF_AL;
        const uint32_t bs_hi = buf + OFF_BH;
        const uint32_t bs_lo = buf + OFF_BL;

#pragma unroll
        for (int kk = 0; kk < 2; kk++) {
            const int ks = kk * 16;
            uint32_t a_hi[2][4], a_lo[2][4];
#pragma unroll
            for (int i = 0; i < 2; i++) {
                const uint32_t off =
                    ((uint32_t)(wm * 32 + i * 16 + lm_row) * LDA + ks + lm_coloff) * 2;
                ldsm_x4(a_hi[i], as_hi + off);
                ldsm_x4(a_lo[i], as_lo + off);
            }
            uint32_t b_hi[8], b_lo[8];
#pragma unroll
            for (int jj = 0; jj < 2; jj++) {
                const uint32_t off =
                    ((uint32_t)(ks + lm_row) * LDB + wn * 32 + jj * 16 + lm_coloff) * 2;
                ldsm_x4_t(&b_hi[jj * 4], bs_hi + off);
                ldsm_x4_t(&b_lo[jj * 4], bs_lo + off);
            }
#pragma unroll
            for (int i = 0; i < 2; i++)
#pragma unroll
                for (int j = 0; j < 4; j++) {
                    mma_bf16(acc[i][j], a_hi[i], &b_hi[j * 2]);
                    mma_bf16(acc[i][j], a_hi[i], &b_lo[j * 2]);
                    mma_bf16(acc[i][j], a_lo[i], &b_hi[j * 2]);
                }
        }
    }

    // ---- epilogue
    const int er = lane >> 2;
    const int ec = (lane & 3) * 2;
#pragma unroll
    for (int i = 0; i < 2; i++) {
        const int r0 = tile_m + wm * 32 + i * 16 + er;
#pragma unroll
        for (int j = 0; j < 4; j++) {
            const int col = tile_n + wn * 32 + j * 8 + ec;
            if (r0 < N_NODES)
                *reinterpret_cast<float2*>(&g_supp[(size_t)r0 * OUT_SIZE + col]) =
                    make_float2(acc[i][j][0], acc[i][j][1]);
            if (r0 + 8 < N_NODES)
                *reinterpret_cast<float2*>(&g_supp[(size_t)(r0 + 8) * OUT_SIZE + col]) =
                    make_float2(acc[i][j][2], acc[i][j][3]);
        }
    }
}

// ---------------------------------------------------------------------------
// CSR build: zero -> histogram -> scan(3) -> fill
// ---------------------------------------------------------------------------
__global__ void zero_deg_kernel() {
    const int i = blockIdx.x * blockDim.x + threadIdx.x;
    if (i < N_NODES) g_deg[i] = 0;
}

__global__ void hist_kernel(const int* __restrict__ edst) {
    const int e = blockIdx.x * blockDim.x + threadIdx.x;
    if (e < N_EDGES) atomicAdd(&g_deg[edst[e]], 1);
}

__global__ __launch_bounds__(1024) void scan1_kernel() {
    __shared__ int s[1024];
    const int tid = threadIdx.x;
    const int i = blockIdx.x * 1024 + tid;
    const int v = (i < N_NODES) ? g_deg[i] : 0;
    s[tid] = v;
    __syncthreads();
#pragma unroll
    for (int d = 1; d < 1024; d <<= 1) {
        int t = (tid >= d) ? s[tid - d] : 0;
        __syncthreads();
        s[tid] += t;
        __syncthreads();
    }
    if (i < N_NODES) g_loc[i] = s[tid] - v;
    if (tid == 1023) g_bsum[blockIdx.x] = s[1023];
}

__global__ __launch_bounds__(128) void scan2_kernel() {
    __shared__ int s[128];
    const int tid = threadIdx.x;
    const int v = (tid < NBLK_SCAN) ? g_bsum[tid] : 0;
    s[tid] = v;
    __syncthreads();
#pragma unroll
    for (int d = 1; d < 128; d <<= 1) {
        int t = (tid >= d) ? s[tid - d] : 0;
        __syncthreads();
        s[tid] += t;
        __syncthreads();
    }
    g_bsum[tid] = s[tid] - v;
}

__global__ void scan3_kernel() {
    const int i = blockIdx.x * blockDim.x + threadIdx.x;
    if (i < N_NODES) {
        const int off = g_loc[i] + g_bsum[i >> 10];
        g_off[i] = off;
        g_cur[i] = off;
    }
    if (i == 0) g_off[N_NODES] = N_EDGES;
}

__global__ void fill_kernel(const float* __restrict__ ew,
                            const int* __restrict__ esrc,
                            const int* __restrict__ edst) {
    const int e = blockIdx.x * blockDim.x + threadIdx.x;
    if (e < N_EDGES) {
        const int p = atomicAdd(&g_cur[edst[e]], 1);
        g_edge[p] = make_uint2((uint32_t)esrc[e], __float_as_uint(ew[e]));
    }
}

// ---------------------------------------------------------------------------
// Aggregate: one warp per destination node. out[d] = sum supp[src]*w + bias
// ---------------------------------------------------------------------------
__global__ __launch_bounds__(256) void aggregate_kernel(const float* __restrict__ bias,
                                                        float* __restrict__ out) {
    const int d = (blockIdx.x * blockDim.x + threadIdx.x) >> 5;
    const int lane = threadIdx.x & 31;
    if (d >= N_NODES) return;

    const int beg = g_off[d];
    const int end = g_off[d + 1];

    float4 acc0 = make_float4(0.f, 0.f, 0.f, 0.f);
    float4 acc1 = make_float4(0.f, 0.f, 0.f, 0.f);

    int p = beg;
    for (; p + 1 < end; p += 2) {
        const uint2 e0 = g_edge[p];
        const uint2 e1 = g_edge[p + 1];
        const float w0 = __uint_as_float(e0.y);
        const float w1 = __uint_as_float(e1.y);
        const float4* s0 = reinterpret_cast<const float4*>(&g_supp[(size_t)e0.x * OUT_SIZE]);
        const float4* s1 = reinterpret_cast<const float4*>(&g_supp[(size_t)e1.x * OUT_SIZE]);
        const float4 a = s0[lane];
        const float4 b = s0[32 + lane];
        const float4 c = s1[lane];
        const float4 dd = s1[32 + lane];
        acc0.x = fmaf(a.x, w0, acc0.x); acc0.y = fmaf(a.y, w0, acc0.y);
        acc0.z = fmaf(a.z, w0, acc0.z); acc0.w = fmaf(a.w, w0, acc0.w);
        acc1.x = fmaf(b.x, w0, acc1.x); acc1.y = fmaf(b.y, w0, acc1.y);
        acc1.z = fmaf(b.z, w0, acc1.z); acc1.w = fmaf(b.w, w0, acc1.w);
        acc0.x = fmaf(c.x, w1, acc0.x); acc0.y = fmaf(c.y, w1, acc0.y);
        acc0.z = fmaf(c.z, w1, acc0.z); acc0.w = fmaf(c.w, w1, acc0.w);
        acc1.x = fmaf(dd.x, w1, acc1.x); acc1.y = fmaf(dd.y, w1, acc1.y);
        acc1.z = fmaf(dd.z, w1, acc1.z); acc1.w = fmaf(dd.w, w1, acc1.w);
    }
    if (p < end) {
        const uint2 e0 = g_edge[p];
        const float w0 = __uint_as_float(e0.y);
        const float4* s0 = reinterpret_cast<const float4*>(&g_supp[(size_t)e0.x * OUT_SIZE]);
        const float4 a = s0[lane];
        const float4 b = s0[32 + lane];
        acc0.x = fmaf(a.x, w0, acc0.x); acc0.y = fmaf(a.y, w0, acc0.y);
        acc0.z = fmaf(a.z, w0, acc0.z); acc0.w = fmaf(a.w, w0, acc0.w);
        acc1.x = fmaf(b.x, w0, acc1.x); acc1.y = fmaf(b.y, w0, acc1.y);
        acc1.z = fmaf(b.z, w0, acc1.z); acc1.w = fmaf(b.w, w0, acc1.w);
    }

    const float4 b0 = reinterpret_cast<const float4*>(bias)[lane];
    const float4 b1 = reinterpret_cast<const float4*>(bias)[32 + lane];
    acc0.x += b0.x; acc0.y += b0.y; acc0.z += b0.z; acc0.w += b0.w;
    acc1.x += b1.x; acc1.y += b1.y; acc1.z += b1.z; acc1.w += b1.w;

    float* op = &out[(size_t)d * OUT_SIZE];
    stcs_f4(op + lane * 4, acc0);
    stcs_f4(op + (32 + lane) * 4, acc1);
}

// ---------------------------------------------------------------------------
extern "C" void kernel_launch(void* const* d_in, const int* in_sizes, int n_in,
                              void* d_out, int out_size) {
    const float* x      = (const float*)d_in[0];
    const float* weight = (const float*)d_in[1];
    const float* bias   = (const float*)d_in[2];
    const float* ew     = (const float*)d_in[3];
    const int*   esrc   = (const int*)d_in[4];
    const int*   edst   = (const int*)d_in[5];
    float* out = (float*)d_out;

    static cudaStream_t s2 = nullptr;
    static cudaEvent_t evA = nullptr, evB = nullptr;
    if (!s2) {
        cudaStreamCreateWithFlags(&s2, cudaStreamNonBlocking);
        cudaEventCreateWithFlags(&evA, cudaEventDisableTiming);
        cudaEventCreateWithFlags(&evB, cudaEventDisableTiming);
        cudaFuncSetAttribute(gemm_hmma_kernel, cudaFuncAttributeMaxDynamicSharedMemorySize,
                             GEMM_SMEM);
    }

    // ---- fork: CSR build on s2, concurrent with GEMM on default stream
    cudaEventRecord(evA, 0);
    cudaStreamWaitEvent(s2, evA, 0);

    zero_deg_kernel<<<(N_NODES + 255) / 256, 256, 0, s2>>>();
    hist_kernel<<<(N_EDGES + 255) / 256, 256, 0, s2>>>(edst);
    scan1_kernel<<<NBLK_SCAN, 1024, 0, s2>>>();
    scan2_kernel<<<1, 128, 0, s2>>>();
    scan3_kernel<<<(N_NODES + 255) / 256, 256, 0, s2>>>();
    fill_kernel<<<(N_EDGES + 255) / 256, 256, 0, s2>>>(ew, esrc, edst);
    cudaEventRecord(evB, s2);

    // ---- main stream: prep + GEMM
    prep_w_kernel<<<IN_SIZE * OUT_SIZE / 256, 256>>>(weight);
    dim3 ggrid(OUT_SIZE / 64, (N_NODES + 127) / 128);
    gemm_hmma_kernel<<<ggrid, 256, GEMM_SMEM>>>(x);

    // ---- join, then aggregate
    cudaStreamWaitEvent(0, evB, 0);
    aggregate_kernel<<<(N_NODES * 32 + 255) / 256, 256>>>(bias, out);
}

// round 9
// speedup vs baseline: 4.4777x; 1.2006x over previous
#include <cuda_runtime.h>
#include <cuda_bf16.h>
#include <cuda_fp16.h>
#include <cstdint>

#define N_NODES 100000
#define N_EDGES 800000
#define IN_SIZE 256
#define OUT_SIZE 256
#define NBLK_SCAN ((N_NODES + 1023) / 1024)   // 98

// ---------------------------------------------------------------------------
// Device scratch
// ---------------------------------------------------------------------------
__device__ __align__(128) __half g_supp_h[(size_t)N_NODES * OUT_SIZE];    // x @ W (fp16)
__device__ __align__(128) __nv_bfloat16 g_w_hi[IN_SIZE * OUT_SIZE];       // W hi [k][n]
__device__ __align__(128) __nv_bfloat16 g_w_lo[IN_SIZE * OUT_SIZE];       // W lo [k][n]

__device__ int   g_deg[N_NODES];
__device__ int   g_loc[N_NODES];
__device__ int   g_bsum[128];
__device__ int   g_off[N_NODES + 1];
__device__ int   g_cur[N_NODES];
__device__ __align__(16) uint2 g_edge[N_EDGES];   // {src, weight bits} grouped by dst

// ---------------------------------------------------------------------------
// Helpers
// ---------------------------------------------------------------------------
__device__ __forceinline__ uint32_t smem_u32(const void* p) {
    uint32_t a;
    asm("{ .reg .u64 t; cvta.to.shared.u64 t, %1; cvt.u32.u64 %0, t; }" : "=r"(a) : "l"(p));
    return a;
}
__device__ __forceinline__ void ldsm_x4(uint32_t* r, uint32_t addr) {
    asm volatile("ldmatrix.sync.aligned.m8n8.x4.shared.b16 {%0,%1,%2,%3}, [%4];"
                 : "=r"(r[0]), "=r"(r[1]), "=r"(r[2]), "=r"(r[3]) : "r"(addr));
}
__device__ __forceinline__ void ldsm_x4_t(uint32_t* r, uint32_t addr) {
    asm volatile("ldmatrix.sync.aligned.m8n8.x4.trans.shared.b16 {%0,%1,%2,%3}, [%4];"
                 : "=r"(r[0]), "=r"(r[1]), "=r"(r[2]), "=r"(r[3]) : "r"(addr));
}
__device__ __forceinline__ void mma_bf16(float* d, const uint32_t* a, const uint32_t* b) {
    asm volatile(
        "mma.sync.aligned.m16n8k16.row.col.f32.bf16.bf16.f32 "
        "{%0,%1,%2,%3}, {%4,%5,%6,%7}, {%8,%9}, {%0,%1,%2,%3};"
        : "+f"(d[0]), "+f"(d[1]), "+f"(d[2]), "+f"(d[3])
        : "r"(a[0]), "r"(a[1]), "r"(a[2]), "r"(a[3]), "r"(b[0]), "r"(b[1]));
}
__device__ __forceinline__ uint32_t bfpack(float x, float y) {
    __nv_bfloat162 t = __floats2bfloat162_rn(x, y);
    return *reinterpret_cast<uint32_t*>(&t);
}
__device__ __forceinline__ void stcs_f4(float* p, float4 v) {
    asm volatile("st.global.cs.v4.f32 [%0], {%1,%2,%3,%4};"
                 :: "l"(p), "f"(v.x), "f"(v.y), "f"(v.z), "f"(v.w) : "memory");
}
__device__ __forceinline__ void cp16(uint32_t dst, const void* src) {
    asm volatile("cp.async.ca.shared.global [%0], [%1], 16;" :: "r"(dst), "l"(src));
}
#define CP_COMMIT() asm volatile("cp.async.commit_group;" ::: "memory")
#define CP_WAIT0()  asm volatile("cp.async.wait_group 0;" ::: "memory")

__device__ __forceinline__ float2 h2f2(uint32_t u) {
    __half2 h = *reinterpret_cast<__half2*>(&u);
    return __half22float2(h);
}

// ---------------------------------------------------------------------------
// Prep: W[k][n] fp32 -> bf16 hi/lo split
// ---------------------------------------------------------------------------
__global__ void prep_w_kernel(const float* __restrict__ W) {
    const int idx = blockIdx.x * blockDim.x + threadIdx.x;
    const float v = W[idx];
    const __nv_bfloat16 h = __float2bfloat16_rn(v);
    g_w_hi[idx] = h;
    g_w_lo[idx] = __float2bfloat16_rn(v - __bfloat162float(h));
}

// ---------------------------------------------------------------------------
// GEMM: supp = x @ W, HMMA bf16 3-term split, double-buffered pipeline.
// CTA 128(M)x64(N), warps 4(M)x2(N) -> warp tile 32x32. 2 CTAs/SM.
// Epilogue stores fp16.
// ---------------------------------------------------------------------------
#define KC 32
#define LDA 40    // bf16 elems per A smem row (32 + 8 pad) = 80 B
#define LDB 72    // bf16 elems per B smem row (64 + 8 pad) = 144 B

#define OFF_AH 0
#define OFF_AL 10240
#define OFF_BH 20480
#define OFF_BL 25088
#define STAGE  29696
#define GEMM_SMEM (2 * STAGE)   // 59392

__global__ __launch_bounds__(256, 2) void gemm_hmma_kernel(const float* __restrict__ X) {
    extern __shared__ __align__(16) char smem[];
    const uint32_t sb = smem_u32(smem);

    const int tid = threadIdx.x;
    const int lane = tid & 31;
    const int w = tid >> 5;
    const int wm = w >> 1;        // 0..3  (M)
    const int wn = w & 1;         // 0..1  (N)
    const int tile_n = blockIdx.x * 64;    // fast dim -> A reuse in L2
    const int tile_m = blockIdx.y * 128;

    float acc[2][4][4];
#pragma unroll
    for (int i = 0; i < 2; i++)
#pragma unroll
        for (int j = 0; j < 4; j++)
#pragma unroll
            for (int q = 0; q < 4; q++) acc[i][j][q] = 0.0f;

    const int a_row = tid >> 3;
    const int a_q = tid & 7;
    const int b_row = tid >> 3;        // 0..31
    const int b_seg = tid & 7;         // 0..7
    const int lm_row = lane & 15;
    const int lm_coloff = (lane >> 4) * 8;

    // ---- prologue
    float4 af[4];
#pragma unroll
    for (int i = 0; i < 4; i++) {
        const int m = tile_m + a_row + i * 32;
        af[i] = make_float4(0.f, 0.f, 0.f, 0.f);
        if (m < N_NODES)
            af[i] = *reinterpret_cast<const float4*>(&X[(size_t)m * IN_SIZE + a_q * 4]);
    }
    {
        const size_t s0 = (size_t)b_row * OUT_SIZE + tile_n + b_seg * 8;
        cp16(sb + OFF_BH + b_row * 144 + b_seg * 16, &g_w_hi[s0]);
        cp16(sb + OFF_BL + b_row * 144 + b_seg * 16, &g_w_lo[s0]);
        CP_COMMIT();
    }

    for (int c = 0; c < IN_SIZE / KC; c++) {
        const int b = c & 1;
        const uint32_t buf = sb + b * STAGE;
        char* bufp = smem + b * STAGE;

        // ---- convert + store A(c)
#pragma unroll
        for (int i = 0; i < 4; i++) {
            const int row = a_row + i * 32;
            const float4 f = af[i];
            const float hx = __bfloat162float(__float2bfloat16_rn(f.x));
            const float hy = __bfloat162float(__float2bfloat16_rn(f.y));
            const float hz = __bfloat162float(__float2bfloat16_rn(f.z));
            const float hw = __bfloat162float(__float2bfloat16_rn(f.w));
            uint2 hv = make_uint2(bfpack(f.x, f.y), bfpack(f.z, f.w));
            uint2 lv = make_uint2(bfpack(f.x - hx, f.y - hy), bfpack(f.z - hz, f.w - hw));
            *reinterpret_cast<uint2*>(bufp + OFF_AH + (row * LDA + a_q * 4) * 2) = hv;
            *reinterpret_cast<uint2*>(bufp + OFF_AL + (row * LDA + a_q * 4) * 2) = lv;
        }

        CP_WAIT0();
        __syncthreads();

        // ---- prefetch next chunk
        if (c + 1 < IN_SIZE / KC) {
            const int k0n = (c + 1) * KC;
#pragma unroll
            for (int i = 0; i < 4; i++) {
                const int m = tile_m + a_row + i * 32;
                af[i] = make_float4(0.f, 0.f, 0.f, 0.f);
                if (m < N_NODES)
                    af[i] = *reinterpret_cast<const float4*>(&X[(size_t)m * IN_SIZE + k0n + a_q * 4]);
            }
            const uint32_t nbuf = sb + (b ^ 1) * STAGE;
            const size_t s0 = (size_t)(k0n + b_row) * OUT_SIZE + tile_n + b_seg * 8;
            cp16(nbuf + OFF_BH + b_row * 144 + b_seg * 16, &g_w_hi[s0]);
            cp16(nbuf + OFF_BL + b_row * 144 + b_seg * 16, &g_w_lo[s0]);
            CP_COMMIT();
        }

        // ---- compute chunk c
        const uint32_t as_hi = buf + OFF_AH;
        const uint32_t as_lo = buf + OFF_AL;
        const uint32_t bs_hi = buf + OFF_BH;
        const uint32_t bs_lo = buf + OFF_BL;

#pragma unroll
        for (int kk = 0; kk < 2; kk++) {
            const int ks = kk * 16;
            uint32_t a_hi[2][4], a_lo[2][4];
#pragma unroll
            for (int i = 0; i < 2; i++) {
                const uint32_t off =
                    ((uint32_t)(wm * 32 + i * 16 + lm_row) * LDA + ks + lm_coloff) * 2;
                ldsm_x4(a_hi[i], as_hi + off);
                ldsm_x4(a_lo[i], as_lo + off);
            }
            uint32_t b_hi[8], b_lo[8];
#pragma unroll
            for (int jj = 0; jj < 2; jj++) {
                const uint32_t off =
                    ((uint32_t)(ks + lm_row) * LDB + wn * 32 + jj * 16 + lm_coloff) * 2;
                ldsm_x4_t(&b_hi[jj * 4], bs_hi + off);
                ldsm_x4_t(&b_lo[jj * 4], bs_lo + off);
            }
#pragma unroll
            for (int i = 0; i < 2; i++)
#pragma unroll
                for (int j = 0; j < 4; j++) {
                    mma_bf16(acc[i][j], a_hi[i], &b_hi[j * 2]);
                    mma_bf16(acc[i][j], a_hi[i], &b_lo[j * 2]);
                    mma_bf16(acc[i][j], a_lo[i], &b_hi[j * 2]);
                }
        }
    }

    // ---- epilogue: fp16 stores
    const int er = lane >> 2;
    const int ec = (lane & 3) * 2;
#pragma unroll
    for (int i = 0; i < 2; i++) {
        const int r0 = tile_m + wm * 32 + i * 16 + er;
#pragma unroll
        for (int j = 0; j < 4; j++) {
            const int col = tile_n + wn * 32 + j * 8 + ec;
            if (r0 < N_NODES) {
                __half2 h = __floats2half2_rn(acc[i][j][0], acc[i][j][1]);
                *reinterpret_cast<__half2*>(&g_supp_h[(size_t)r0 * OUT_SIZE + col]) = h;
            }
            if (r0 + 8 < N_NODES) {
                __half2 h = __floats2half2_rn(acc[i][j][2], acc[i][j][3]);
                *reinterpret_cast<__half2*>(&g_supp_h[(size_t)(r0 + 8) * OUT_SIZE + col]) = h;
            }
        }
    }
}

// ---------------------------------------------------------------------------
// CSR build: zero -> histogram -> scan(3) -> fill
// ---------------------------------------------------------------------------
__global__ void zero_deg_kernel() {
    const int i = blockIdx.x * blockDim.x + threadIdx.x;
    if (i < N_NODES) g_deg[i] = 0;
}

__global__ void hist_kernel(const int* __restrict__ edst) {
    const int e = blockIdx.x * blockDim.x + threadIdx.x;
    if (e < N_EDGES) atomicAdd(&g_deg[edst[e]], 1);
}

__global__ __launch_bounds__(1024) void scan1_kernel() {
    __shared__ int s[1024];
    const int tid = threadIdx.x;
    const int i = blockIdx.x * 1024 + tid;
    const int v = (i < N_NODES) ? g_deg[i] : 0;
    s[tid] = v;
    __syncthreads();
#pragma unroll
    for (int d = 1; d < 1024; d <<= 1) {
        int t = (tid >= d) ? s[tid - d] : 0;
        __syncthreads();
        s[tid] += t;
        __syncthreads();
    }
    if (i < N_NODES) g_loc[i] = s[tid] - v;
    if (tid == 1023) g_bsum[blockIdx.x] = s[1023];
}

__global__ __launch_bounds__(128) void scan2_kernel() {
    __shared__ int s[128];
    const int tid = threadIdx.x;
    const int v = (tid < NBLK_SCAN) ? g_bsum[tid] : 0;
    s[tid] = v;
    __syncthreads();
#pragma unroll
    for (int d = 1; d < 128; d <<= 1) {
        int t = (tid >= d) ? s[tid - d] : 0;
        __syncthreads();
        s[tid] += t;
        __syncthreads();
    }
    g_bsum[tid] = s[tid] - v;
}

__global__ void scan3_kernel() {
    const int i = blockIdx.x * blockDim.x + threadIdx.x;
    if (i < N_NODES) {
        const int off = g_loc[i] + g_bsum[i >> 10];
        g_off[i] = off;
        g_cur[i] = off;
    }
    if (i == 0) g_off[N_NODES] = N_EDGES;
}

__global__ void fill_kernel(const float* __restrict__ ew,
                            const int* __restrict__ esrc,
                            const int* __restrict__ edst) {
    const int e = blockIdx.x * blockDim.x + threadIdx.x;
    if (e < N_EDGES) {
        const int p = atomicAdd(&g_cur[edst[e]], 1);
        g_edge[p] = make_uint2((uint32_t)esrc[e], __float_as_uint(ew[e]));
    }
}

// ---------------------------------------------------------------------------
// Aggregate: one warp per dst node. out[d] = sum supp_h[src]*w + bias.
// fp16 gather: one uint4 (8 halves) per lane per edge.
// ---------------------------------------------------------------------------
__global__ __launch_bounds__(256) void aggregate_kernel(const float* __restrict__ bias,
                                                        float* __restrict__ out) {
    const int d = (blockIdx.x * blockDim.x + threadIdx.x) >> 5;
    const int lane = threadIdx.x & 31;
    if (d >= N_NODES) return;

    const int beg = g_off[d];
    const int end = g_off[d + 1];

    // acc initialized with bias; lane covers columns [lane*8, lane*8+8)
    float4 acc0 = reinterpret_cast<const float4*>(bias)[lane * 2];
    float4 acc1 = reinterpret_cast<const float4*>(bias)[lane * 2 + 1];

    int p = beg;
    for (; p + 1 < end; p += 2) {
        const uint2 e0 = g_edge[p];
        const uint2 e1 = g_edge[p + 1];
        const float w0 = __uint_as_float(e0.y);
        const float w1 = __uint_as_float(e1.y);
        const uint4 v0 = *reinterpret_cast<const uint4*>(
            &g_supp_h[(size_t)e0.x * OUT_SIZE + lane * 8]);
        const uint4 v1 = *reinterpret_cast<const uint4*>(
            &g_supp_h[(size_t)e1.x * OUT_SIZE + lane * 8]);

        float2 f;
        f = h2f2(v0.x); acc0.x = fmaf(f.x, w0, acc0.x); acc0.y = fmaf(f.y, w0, acc0.y);
        f = h2f2(v0.y); acc0.z = fmaf(f.x, w0, acc0.z); acc0.w = fmaf(f.y, w0, acc0.w);
        f = h2f2(v0.z); acc1.x = fmaf(f.x, w0, acc1.x); acc1.y = fmaf(f.y, w0, acc1.y);
        f = h2f2(v0.w); acc1.z = fmaf(f.x, w0, acc1.z); acc1.w = fmaf(f.y, w0, acc1.w);

        f = h2f2(v1.x); acc0.x = fmaf(f.x, w1, acc0.x); acc0.y = fmaf(f.y, w1, acc0.y);
        f = h2f2(v1.y); acc0.z = fmaf(f.x, w1, acc0.z); acc0.w = fmaf(f.y, w1, acc0.w);
        f = h2f2(v1.z); acc1.x = fmaf(f.x, w1, acc1.x); acc1.y = fmaf(f.y, w1, acc1.y);
        f = h2f2(v1.w); acc1.z = fmaf(f.x, w1, acc1.z); acc1.w = fmaf(f.y, w1, acc1.w);
    }
    if (p < end) {
        const uint2 e0 = g_edge[p];
        const float w0 = __uint_as_float(e0.y);
        const uint4 v0 = *reinterpret_cast<const uint4*>(
            &g_supp_h[(size_t)e0.x * OUT_SIZE + lane * 8]);
        float2 f;
        f = h2f2(v0.x); acc0.x = fmaf(f.x, w0, acc0.x); acc0.y = fmaf(f.y, w0, acc0.y);
        f = h2f2(v0.y); acc0.z = fmaf(f.x, w0, acc0.z); acc0.w = fmaf(f.y, w0, acc0.w);
        f = h2f2(v0.z); acc1.x = fmaf(f.x, w0, acc1.x); acc1.y = fmaf(f.y, w0, acc1.y);
        f = h2f2(v0.w); acc1.z = fmaf(f.x, w0, acc1.z); acc1.w = fmaf(f.y, w0, acc1.w);
    }

    float* op = &out[(size_t)d * OUT_SIZE + lane * 8];
    stcs_f4(op, acc0);
    stcs_f4(op + 4, acc1);
}

// ---------------------------------------------------------------------------
extern "C" void kernel_launch(void* const* d_in, const int* in_sizes, int n_in,
                              void* d_out, int out_size) {
    const float* x      = (const float*)d_in[0];
    const float* weight = (const float*)d_in[1];
    const float* bias   = (const float*)d_in[2];
    const float* ew     = (const float*)d_in[3];
    const int*   esrc   = (const int*)d_in[4];
    const int*   edst   = (const int*)d_in[5];
    float* out = (float*)d_out;

    static cudaStream_t s2 = nullptr;
    static cudaEvent_t evA = nullptr, evB = nullptr;
    if (!s2) {
        cudaStreamCreateWithFlags(&s2, cudaStreamNonBlocking);
        cudaEventCreateWithFlags(&evA, cudaEventDisableTiming);
        cudaEventCreateWithFlags(&evB, cudaEventDisableTiming);
        cudaFuncSetAttribute(gemm_hmma_kernel, cudaFuncAttributeMaxDynamicSharedMemorySize,
                             GEMM_SMEM);
    }

    // ---- fork: CSR build on s2, concurrent with GEMM on default stream
    cudaEventRecord(evA, 0);
    cudaStreamWaitEvent(s2, evA, 0);

    zero_deg_kernel<<<(N_NODES + 255) / 256, 256, 0, s2>>>();
    hist_kernel<<<(N_EDGES + 255) / 256, 256, 0, s2>>>(edst);
    scan1_kernel<<<NBLK_SCAN, 1024, 0, s2>>>();
    scan2_kernel<<<1, 128, 0, s2>>>();
    scan3_kernel<<<(N_NODES + 255) / 256, 256, 0, s2>>>();
    fill_kernel<<<(N_EDGES + 255) / 256, 256, 0, s2>>>(ew, esrc, edst);
    cudaEventRecord(evB, s2);

    // ---- main stream: prep + GEMM
    prep_w_kernel<<<IN_SIZE * OUT_SIZE / 256, 256>>>(weight);
    dim3 ggrid(OUT_SIZE / 64, (N_NODES + 127) / 128);
    gemm_hmma_kernel<<<ggrid, 256, GEMM_SMEM>>>(x);

    // ---- join, then aggregate
    cudaStreamWaitEvent(0, evB, 0);
    aggregate_kernel<<<(N_NODES * 32 + 255) / 256, 256>>>(bias, out);
}

// round 10
// speedup vs baseline: 4.9921x; 1.1149x over previous
#include <cuda_runtime.h>
#include <cuda_bf16.h>
#include <cuda_fp16.h>
#include <cstdint>

#define N_NODES 100000
#define N_EDGES 800000
#define IN_SIZE 256
#define OUT_SIZE 256
#define NBLK_SCAN ((N_NODES + 1023) / 1024)   // 98

// ---------------------------------------------------------------------------
// Device scratch
// ---------------------------------------------------------------------------
__device__ __align__(128) __half g_supp_h[(size_t)N_NODES * OUT_SIZE];    // x @ W (fp16)
__device__ __align__(128) __half g_w_h[IN_SIZE * OUT_SIZE];               // W fp16 [k][n]

__device__ int   g_deg[N_NODES];
__device__ int   g_loc[N_NODES];
__device__ int   g_bsum[128];
__device__ int   g_off[N_NODES + 1];
__device__ int   g_cur[N_NODES];
__device__ __align__(16) uint2 g_edge[N_EDGES];   // {src, weight bits} grouped by dst

// ---------------------------------------------------------------------------
// Helpers
// ---------------------------------------------------------------------------
__device__ __forceinline__ uint32_t smem_u32(const void* p) {
    uint32_t a;
    asm("{ .reg .u64 t; cvta.to.shared.u64 t, %1; cvt.u32.u64 %0, t; }" : "=r"(a) : "l"(p));
    return a;
}
__device__ __forceinline__ void ldsm_x4(uint32_t* r, uint32_t addr) {
    asm volatile("ldmatrix.sync.aligned.m8n8.x4.shared.b16 {%0,%1,%2,%3}, [%4];"
                 : "=r"(r[0]), "=r"(r[1]), "=r"(r[2]), "=r"(r[3]) : "r"(addr));
}
__device__ __forceinline__ void ldsm_x4_t(uint32_t* r, uint32_t addr) {
    asm volatile("ldmatrix.sync.aligned.m8n8.x4.trans.shared.b16 {%0,%1,%2,%3}, [%4];"
                 : "=r"(r[0]), "=r"(r[1]), "=r"(r[2]), "=r"(r[3]) : "r"(addr));
}
__device__ __forceinline__ void mma_f16(float* d, const uint32_t* a, const uint32_t* b) {
    asm volatile(
        "mma.sync.aligned.m16n8k16.row.col.f32.f16.f16.f32 "
        "{%0,%1,%2,%3}, {%4,%5,%6,%7}, {%8,%9}, {%0,%1,%2,%3};"
        : "+f"(d[0]), "+f"(d[1]), "+f"(d[2]), "+f"(d[3])
        : "r"(a[0]), "r"(a[1]), "r"(a[2]), "r"(a[3]), "r"(b[0]), "r"(b[1]));
}
__device__ __forceinline__ uint32_t hpack(float x, float y) {
    __half2 t = __floats2half2_rn(x, y);
    return *reinterpret_cast<uint32_t*>(&t);
}
__device__ __forceinline__ void stcs_f4(float* p, float4 v) {
    asm volatile("st.global.cs.v4.f32 [%0], {%1,%2,%3,%4};"
                 :: "l"(p), "f"(v.x), "f"(v.y), "f"(v.z), "f"(v.w) : "memory");
}
__device__ __forceinline__ void cp16(uint32_t dst, const void* src) {
    asm volatile("cp.async.ca.shared.global [%0], [%1], 16;" :: "r"(dst), "l"(src));
}
#define CP_COMMIT() asm volatile("cp.async.commit_group;" ::: "memory")
#define CP_WAIT0()  asm volatile("cp.async.wait_group 0;" ::: "memory")

__device__ __forceinline__ float2 h2f2(uint32_t u) {
    __half2 h = *reinterpret_cast<__half2*>(&u);
    return __half22float2(h);
}

// ---------------------------------------------------------------------------
// Prep: W[k][n] fp32 -> fp16
// ---------------------------------------------------------------------------
__global__ void prep_w_kernel(const float* __restrict__ W) {
    const int idx = blockIdx.x * blockDim.x + threadIdx.x;
    g_w_h[idx] = __float2half_rn(W[idx]);
}

// ---------------------------------------------------------------------------
// GEMM: supp = x @ W, HMMA fp16 2-term split (A = hi+lo fp16, W single fp16).
// CTA 128(M)x64(N), warps 4(M)x2(N) -> warp tile 32x32. 2 CTAs/SM.
// Double-buffered smem pipeline; epilogue stores fp16.
// ---------------------------------------------------------------------------
#define KC 32
#define LDA 40    // fp16 elems per A smem row (32 + 8 pad) = 80 B
#define LDB 72    // fp16 elems per B smem row (64 + 8 pad) = 144 B

#define OFF_AH 0
#define OFF_AL 10240
#define OFF_B  20480
#define STAGE  25088           // 20480 + 32*144 = 25088
#define GEMM_SMEM (2 * STAGE)  // 50176

__global__ __launch_bounds__(256, 2) void gemm_hmma_kernel(const float* __restrict__ X) {
    extern __shared__ __align__(16) char smem[];
    const uint32_t sb = smem_u32(smem);

    const int tid = threadIdx.x;
    const int lane = tid & 31;
    const int w = tid >> 5;
    const int wm = w >> 1;        // 0..3  (M)
    const int wn = w & 1;         // 0..1  (N)
    const int tile_n = blockIdx.x * 64;    // fast dim -> A reuse in L2
    const int tile_m = blockIdx.y * 128;

    float acc[2][4][4];
#pragma unroll
    for (int i = 0; i < 2; i++)
#pragma unroll
        for (int j = 0; j < 4; j++)
#pragma unroll
            for (int q = 0; q < 4; q++) acc[i][j][q] = 0.0f;

    const int a_row = tid >> 3;
    const int a_q = tid & 7;
    const int b_row = tid >> 3;        // 0..31
    const int b_seg = tid & 7;         // 0..7
    const int lm_row = lane & 15;
    const int lm_coloff = (lane >> 4) * 8;

    // ---- prologue: LDG A(0), cp.async B(0)
    float4 af[4];
#pragma unroll
    for (int i = 0; i < 4; i++) {
        const int m = tile_m + a_row + i * 32;
        af[i] = make_float4(0.f, 0.f, 0.f, 0.f);
        if (m < N_NODES)
            af[i] = *reinterpret_cast<const float4*>(&X[(size_t)m * IN_SIZE + a_q * 4]);
    }
    {
        const size_t s0 = (size_t)b_row * OUT_SIZE + tile_n + b_seg * 8;
        cp16(sb + OFF_B + b_row * 144 + b_seg * 16, &g_w_h[s0]);
        CP_COMMIT();
    }

    for (int c = 0; c < IN_SIZE / KC; c++) {
        const int b = c & 1;
        const uint32_t buf = sb + b * STAGE;
        char* bufp = smem + b * STAGE;

        // ---- split + store A(c): fp16 hi/lo
#pragma unroll
        for (int i = 0; i < 4; i++) {
            const int row = a_row + i * 32;
            const float4 f = af[i];
            const float hx = __half2float(__float2half_rn(f.x));
            const float hy = __half2float(__float2half_rn(f.y));
            const float hz = __half2float(__float2half_rn(f.z));
            const float hw = __half2float(__float2half_rn(f.w));
            uint2 hv = make_uint2(hpack(f.x, f.y), hpack(f.z, f.w));
            uint2 lv = make_uint2(hpack(f.x - hx, f.y - hy), hpack(f.z - hz, f.w - hw));
            *reinterpret_cast<uint2*>(bufp + OFF_AH + (row * LDA + a_q * 4) * 2) = hv;
            *reinterpret_cast<uint2*>(bufp + OFF_AL + (row * LDA + a_q * 4) * 2) = lv;
        }

        CP_WAIT0();
        __syncthreads();

        // ---- prefetch next chunk (overlaps compute)
        if (c + 1 < IN_SIZE / KC) {
            const int k0n = (c + 1) * KC;
#pragma unroll
            for (int i = 0; i < 4; i++) {
                const int m = tile_m + a_row + i * 32;
                af[i] = make_float4(0.f, 0.f, 0.f, 0.f);
                if (m < N_NODES)
                    af[i] = *reinterpret_cast<const float4*>(&X[(size_t)m * IN_SIZE + k0n + a_q * 4]);
            }
            const uint32_t nbuf = sb + (b ^ 1) * STAGE;
            const size_t s0 = (size_t)(k0n + b_row) * OUT_SIZE + tile_n + b_seg * 8;
            cp16(nbuf + OFF_B + b_row * 144 + b_seg * 16, &g_w_h[s0]);
            CP_COMMIT();
        }

        // ---- compute chunk c
        const uint32_t as_hi = buf + OFF_AH;
        const uint32_t as_lo = buf + OFF_AL;
        const uint32_t bs = buf + OFF_B;

#pragma unroll
        for (int kk = 0; kk < 2; kk++) {
            const int ks = kk * 16;
            uint32_t a_hi[2][4], a_lo[2][4];
#pragma unroll
            for (int i = 0; i < 2; i++) {
                const uint32_t off =
                    ((uint32_t)(wm * 32 + i * 16 + lm_row) * LDA + ks + lm_coloff) * 2;
                ldsm_x4(a_hi[i], as_hi + off);
                ldsm_x4(a_lo[i], as_lo + off);
            }
            uint32_t bm[8];
#pragma unroll
            for (int jj = 0; jj < 2; jj++) {
                const uint32_t off =
                    ((uint32_t)(ks + lm_row) * LDB + wn * 32 + jj * 16 + lm_coloff) * 2;
                ldsm_x4_t(&bm[jj * 4], bs + off);
            }
#pragma unroll
            for (int i = 0; i < 2; i++)
#pragma unroll
                for (int j = 0; j < 4; j++) {
                    mma_f16(acc[i][j], a_hi[i], &bm[j * 2]);
                    mma_f16(acc[i][j], a_lo[i], &bm[j * 2]);
                }
        }
    }

    // ---- epilogue: fp16 stores
    const int er = lane >> 2;
    const int ec = (lane & 3) * 2;
#pragma unroll
    for (int i = 0; i < 2; i++) {
        const int r0 = tile_m + wm * 32 + i * 16 + er;
#pragma unroll
        for (int j = 0; j < 4; j++) {
            const int col = tile_n + wn * 32 + j * 8 + ec;
            if (r0 < N_NODES) {
                __half2 h = __floats2half2_rn(acc[i][j][0], acc[i][j][1]);
                *reinterpret_cast<__half2*>(&g_supp_h[(size_t)r0 * OUT_SIZE + col]) = h;
            }
            if (r0 + 8 < N_NODES) {
                __half2 h = __floats2half2_rn(acc[i][j][2], acc[i][j][3]);
                *reinterpret_cast<__half2*>(&g_supp_h[(size_t)(r0 + 8) * OUT_SIZE + col]) = h;
            }
        }
    }
}

// ---------------------------------------------------------------------------
// CSR build: zero -> histogram -> scan(3) -> fill
// ---------------------------------------------------------------------------
__global__ void zero_deg_kernel() {
    const int i = blockIdx.x * blockDim.x + threadIdx.x;
    if (i < N_NODES) g_deg[i] = 0;
}

__global__ void hist_kernel(const int* __restrict__ edst) {
    const int e = blockIdx.x * blockDim.x + threadIdx.x;
    if (e < N_EDGES) atomicAdd(&g_deg[edst[e]], 1);
}

__global__ __launch_bounds__(1024) void scan1_kernel() {
    __shared__ int s[1024];
    const int tid = threadIdx.x;
    const int i = blockIdx.x * 1024 + tid;
    const int v = (i < N_NODES) ? g_deg[i] : 0;
    s[tid] = v;
    __syncthreads();
#pragma unroll
    for (int d = 1; d < 1024; d <<= 1) {
        int t = (tid >= d) ? s[tid - d] : 0;
        __syncthreads();
        s[tid] += t;
        __syncthreads();
    }
    if (i < N_NODES) g_loc[i] = s[tid] - v;
    if (tid == 1023) g_bsum[blockIdx.x] = s[1023];
}

__global__ __launch_bounds__(128) void scan2_kernel() {
    __shared__ int s[128];
    const int tid = threadIdx.x;
    const int v = (tid < NBLK_SCAN) ? g_bsum[tid] : 0;
    s[tid] = v;
    __syncthreads();
#pragma unroll
    for (int d = 1; d < 128; d <<= 1) {
        int t = (tid >= d) ? s[tid - d] : 0;
        __syncthreads();
        s[tid] += t;
        __syncthreads();
    }
    g_bsum[tid] = s[tid] - v;
}

__global__ void scan3_kernel() {
    const int i = blockIdx.x * blockDim.x + threadIdx.x;
    if (i < N_NODES) {
        const int off = g_loc[i] + g_bsum[i >> 10];
        g_off[i] = off;
        g_cur[i] = off;
    }
    if (i == 0) g_off[N_NODES] = N_EDGES;
}

__global__ void fill_kernel(const float* __restrict__ ew,
                            const int* __restrict__ esrc,
                            const int* __restrict__ edst) {
    const int e = blockIdx.x * blockDim.x + threadIdx.x;
    if (e < N_EDGES) {
        const int p = atomicAdd(&g_cur[edst[e]], 1);
        g_edge[p] = make_uint2((uint32_t)esrc[e], __float_as_uint(ew[e]));
    }
}

// ---------------------------------------------------------------------------
// Aggregate: one warp per dst node. out[d] = sum supp_h[src]*w + bias.
// fp16 gather: one uint4 (8 halves) per lane per edge.
// ---------------------------------------------------------------------------
__global__ __launch_bounds__(256) void aggregate_kernel(const float* __restrict__ bias,
                                                        float* __restrict__ out) {
    const int d = (blockIdx.x * blockDim.x + threadIdx.x) >> 5;
    const int lane = threadIdx.x & 31;
    if (d >= N_NODES) return;

    const int beg = g_off[d];
    const int end = g_off[d + 1];

    float4 acc0 = reinterpret_cast<const float4*>(bias)[lane * 2];
    float4 acc1 = reinterpret_cast<const float4*>(bias)[lane * 2 + 1];

    int p = beg;
    for (; p + 1 < end; p += 2) {
        const uint2 e0 = g_edge[p];
        const uint2 e1 = g_edge[p + 1];
        const float w0 = __uint_as_float(e0.y);
        const float w1 = __uint_as_float(e1.y);
        const uint4 v0 = *reinterpret_cast<const uint4*>(
            &g_supp_h[(size_t)e0.x * OUT_SIZE + lane * 8]);
        const uint4 v1 = *reinterpret_cast<const uint4*>(
            &g_supp_h[(size_t)e1.x * OUT_SIZE + lane * 8]);

        float2 f;
        f = h2f2(v0.x); acc0.x = fmaf(f.x, w0, acc0.x); acc0.y = fmaf(f.y, w0, acc0.y);
        f = h2f2(v0.y); acc0.z = fmaf(f.x, w0, acc0.z); acc0.w = fmaf(f.y, w0, acc0.w);
        f = h2f2(v0.z); acc1.x = fmaf(f.x, w0, acc1.x); acc1.y = fmaf(f.y, w0, acc1.y);
        f = h2f2(v0.w); acc1.z = fmaf(f.x, w0, acc1.z); acc1.w = fmaf(f.y, w0, acc1.w);

        f = h2f2(v1.x); acc0.x = fmaf(f.x, w1, acc0.x); acc0.y = fmaf(f.y, w1, acc0.y);
        f = h2f2(v1.y); acc0.z = fmaf(f.x, w1, acc0.z); acc0.w = fmaf(f.y, w1, acc0.w);
        f = h2f2(v1.z); acc1.x = fmaf(f.x, w1, acc1.x); acc1.y = fmaf(f.y, w1, acc1.y);
        f = h2f2(v1.w); acc1.z = fmaf(f.x, w1, acc1.z); acc1.w = fmaf(f.y, w1, acc1.w);
    }
    if (p < end) {
        const uint2 e0 = g_edge[p];
        const float w0 = __uint_as_float(e0.y);
        const uint4 v0 = *reinterpret_cast<const uint4*>(
            &g_supp_h[(size_t)e0.x * OUT_SIZE + lane * 8]);
        float2 f;
        f = h2f2(v0.x); acc0.x = fmaf(f.x, w0, acc0.x); acc0.y = fmaf(f.y, w0, acc0.y);
        f = h2f2(v0.y); acc0.z = fmaf(f.x, w0, acc0.z); acc0.w = fmaf(f.y, w0, acc0.w);
        f = h2f2(v0.z); acc1.x = fmaf(f.x, w0, acc1.x); acc1.y = fmaf(f.y, w0, acc1.y);
        f = h2f2(v0.w); acc1.z = fmaf(f.x, w0, acc1.z); acc1.w = fmaf(f.y, w0, acc1.w);
    }

    float* op = &out[(size_t)d * OUT_SIZE + lane * 8];
    stcs_f4(op, acc0);
    stcs_f4(op + 4, acc1);
}

// ---------------------------------------------------------------------------
extern "C" void kernel_launch(void* const* d_in, const int* in_sizes, int n_in,
                              void* d_out, int out_size) {
    const float* x      = (const float*)d_in[0];
    const float* weight = (const float*)d_in[1];
    const float* bias   = (const float*)d_in[2];
    const float* ew     = (const float*)d_in[3];
    const int*   esrc   = (const int*)d_in[4];
    const int*   edst   = (const int*)d_in[5];
    float* out = (float*)d_out;

    static cudaStream_t s2 = nullptr;
    static cudaEvent_t evA = nullptr, evB = nullptr;
    if (!s2) {
        cudaStreamCreateWithFlags(&s2, cudaStreamNonBlocking);
        cudaEventCreateWithFlags(&evA, cudaEventDisableTiming);
        cudaEventCreateWithFlags(&evB, cudaEventDisableTiming);
        cudaFuncSetAttribute(gemm_hmma_kernel, cudaFuncAttributeMaxDynamicSharedMemorySize,
                             GEMM_SMEM);
    }

    // ---- fork: CSR build on s2, concurrent with GEMM on default stream
    cudaEventRecord(evA, 0);
    cudaStreamWaitEvent(s2, evA, 0);

    zero_deg_kernel<<<(N_NODES + 255) / 256, 256, 0, s2>>>();
    hist_kernel<<<(N_EDGES + 255) / 256, 256, 0, s2>>>(edst);
    scan1_kernel<<<NBLK_SCAN, 1024, 0, s2>>>();
    scan2_kernel<<<1, 128, 0, s2>>>();
    scan3_kernel<<<(N_NODES + 255) / 256, 256, 0, s2>>>();
    fill_kernel<<<(N_EDGES + 255) / 256, 256, 0, s2>>>(ew, esrc, edst);
    cudaEventRecord(evB, s2);

    // ---- main stream: prep + GEMM
    prep_w_kernel<<<IN_SIZE * OUT_SIZE / 256, 256>>>(weight);
    dim3 ggrid(OUT_SIZE / 64, (N_NODES + 127) / 128);
    gemm_hmma_kernel<<<ggrid, 256, GEMM_SMEM>>>(x);

    // ---- join, then aggregate
    cudaStreamWaitEvent(0, evB, 0);
    aggregate_kernel<<<(N_NODES * 32 + 255) / 256, 256>>>(bias, out);
}

// round 11
// speedup vs baseline: 5.3786x; 1.0774x over previous
#include <cuda_runtime.h>
#include <cuda_bf16.h>
#include <cuda_fp16.h>
#include <cstdint>

#define N_NODES 100000
#define N_EDGES 800000
#define IN_SIZE 256
#define OUT_SIZE 256
#define NBLK_SCAN ((N_NODES + 1023) / 1024)   // 98

// ---------------------------------------------------------------------------
// Device scratch
// ---------------------------------------------------------------------------
__device__ __align__(128) __half g_supp_h[(size_t)N_NODES * OUT_SIZE];    // x @ W (fp16)
__device__ __align__(128) __half g_w_h[IN_SIZE * OUT_SIZE];               // W fp16 [k][n]

__device__ int   g_deg[N_NODES];
__device__ int   g_loc[N_NODES];
__device__ int   g_bsum[128];
__device__ int   g_off[N_NODES + 1];
__device__ int   g_cur[N_NODES];
__device__ __align__(16) uint2 g_edge[N_EDGES];   // {src, weight bits} grouped by dst

// ---------------------------------------------------------------------------
// Helpers
// ---------------------------------------------------------------------------
__device__ __forceinline__ uint32_t smem_u32(const void* p) {
    uint32_t a;
    asm("{ .reg .u64 t; cvta.to.shared.u64 t, %1; cvt.u32.u64 %0, t; }" : "=r"(a) : "l"(p));
    return a;
}
__device__ __forceinline__ void ldsm_x4(uint32_t* r, uint32_t addr) {
    asm volatile("ldmatrix.sync.aligned.m8n8.x4.shared.b16 {%0,%1,%2,%3}, [%4];"
                 : "=r"(r[0]), "=r"(r[1]), "=r"(r[2]), "=r"(r[3]) : "r"(addr));
}
__device__ __forceinline__ void ldsm_x4_t(uint32_t* r, uint32_t addr) {
    asm volatile("ldmatrix.sync.aligned.m8n8.x4.trans.shared.b16 {%0,%1,%2,%3}, [%4];"
                 : "=r"(r[0]), "=r"(r[1]), "=r"(r[2]), "=r"(r[3]) : "r"(addr));
}
__device__ __forceinline__ void mma_f16(float* d, const uint32_t* a, const uint32_t* b) {
    asm volatile(
        "mma.sync.aligned.m16n8k16.row.col.f32.f16.f16.f32 "
        "{%0,%1,%2,%3}, {%4,%5,%6,%7}, {%8,%9}, {%0,%1,%2,%3};"
        : "+f"(d[0]), "+f"(d[1]), "+f"(d[2]), "+f"(d[3])
        : "r"(a[0]), "r"(a[1]), "r"(a[2]), "r"(a[3]), "r"(b[0]), "r"(b[1]));
}
__device__ __forceinline__ uint32_t hpack(float x, float y) {
    __half2 t = __floats2half2_rn(x, y);
    return *reinterpret_cast<uint32_t*>(&t);
}
__device__ __forceinline__ void stcs_f4(float* p, float4 v) {
    asm volatile("st.global.cs.v4.f32 [%0], {%1,%2,%3,%4};"
                 :: "l"(p), "f"(v.x), "f"(v.y), "f"(v.z), "f"(v.w) : "memory");
}
__device__ __forceinline__ void cp16(uint32_t dst, const void* src) {
    asm volatile("cp.async.ca.shared.global [%0], [%1], 16;" :: "r"(dst), "l"(src));
}
#define CP_COMMIT() asm volatile("cp.async.commit_group;" ::: "memory")
#define CP_WAIT0()  asm volatile("cp.async.wait_group 0;" ::: "memory")

__device__ __forceinline__ float2 h2f2(uint32_t u) {
    __half2 h = *reinterpret_cast<__half2*>(&u);
    return __half22float2(h);
}

// ---------------------------------------------------------------------------
// Prep: W[k][n] fp32 -> fp16
// ---------------------------------------------------------------------------
__global__ void prep_w_kernel(const float* __restrict__ W) {
    const int idx = blockIdx.x * blockDim.x + threadIdx.x;
    g_w_h[idx] = __float2half_rn(W[idx]);
}

// ---------------------------------------------------------------------------
// GEMM: supp = x @ W, plain fp16 HMMA (A fp16, W fp16, fp32 accum).
// CTA 128(M)x64(N), warps 4(M)x2(N) -> warp tile 32x32. 2 CTAs/SM.
// Double-buffered smem pipeline; epilogue stores fp16.
// ---------------------------------------------------------------------------
#define KC 32
#define LDA 40    // fp16 elems per A smem row (32 + 8 pad) = 80 B
#define LDB 72    // fp16 elems per B smem row (64 + 8 pad) = 144 B

#define OFF_A  0
#define OFF_B  10240
#define STAGE  14848           // 10240 + 32*144
#define GEMM_SMEM (2 * STAGE)  // 29696

__global__ __launch_bounds__(256, 2) void gemm_hmma_kernel(const float* __restrict__ X) {
    extern __shared__ __align__(16) char smem[];
    const uint32_t sb = smem_u32(smem);

    const int tid = threadIdx.x;
    const int lane = tid & 31;
    const int w = tid >> 5;
    const int wm = w >> 1;        // 0..3  (M)
    const int wn = w & 1;         // 0..1  (N)
    const int tile_n = blockIdx.x * 64;    // fast dim -> A reuse in L2
    const int tile_m = blockIdx.y * 128;

    float acc[2][4][4];
#pragma unroll
    for (int i = 0; i < 2; i++)
#pragma unroll
        for (int j = 0; j < 4; j++)
#pragma unroll
            for (int q = 0; q < 4; q++) acc[i][j][q] = 0.0f;

    const int a_row = tid >> 3;
    const int a_q = tid & 7;
    const int b_row = tid >> 3;        // 0..31
    const int b_seg = tid & 7;         // 0..7
    const int lm_row = lane & 15;
    const int lm_coloff = (lane >> 4) * 8;

    // ---- prologue: LDG A(0), cp.async B(0)
    float4 af[4];
#pragma unroll
    for (int i = 0; i < 4; i++) {
        const int m = tile_m + a_row + i * 32;
        af[i] = make_float4(0.f, 0.f, 0.f, 0.f);
        if (m < N_NODES)
            af[i] = *reinterpret_cast<const float4*>(&X[(size_t)m * IN_SIZE + a_q * 4]);
    }
    {
        const size_t s0 = (size_t)b_row * OUT_SIZE + tile_n + b_seg * 8;
        cp16(sb + OFF_B + b_row * 144 + b_seg * 16, &g_w_h[s0]);
        CP_COMMIT();
    }

    for (int c = 0; c < IN_SIZE / KC; c++) {
        const int b = c & 1;
        const uint32_t buf = sb + b * STAGE;
        char* bufp = smem + b * STAGE;

        // ---- convert + store A(c): single fp16
#pragma unroll
        for (int i = 0; i < 4; i++) {
            const int row = a_row + i * 32;
            const float4 f = af[i];
            uint2 hv = make_uint2(hpack(f.x, f.y), hpack(f.z, f.w));
            *reinterpret_cast<uint2*>(bufp + OFF_A + (row * LDA + a_q * 4) * 2) = hv;
        }

        CP_WAIT0();
        __syncthreads();

        // ---- prefetch next chunk (overlaps compute)
        if (c + 1 < IN_SIZE / KC) {
            const int k0n = (c + 1) * KC;
#pragma unroll
            for (int i = 0; i < 4; i++) {
                const int m = tile_m + a_row + i * 32;
                af[i] = make_float4(0.f, 0.f, 0.f, 0.f);
                if (m < N_NODES)
                    af[i] = *reinterpret_cast<const float4*>(&X[(size_t)m * IN_SIZE + k0n + a_q * 4]);
            }
            const uint32_t nbuf = sb + (b ^ 1) * STAGE;
            const size_t s0 = (size_t)(k0n + b_row) * OUT_SIZE + tile_n + b_seg * 8;
            cp16(nbuf + OFF_B + b_row * 144 + b_seg * 16, &g_w_h[s0]);
            CP_COMMIT();
        }

        // ---- compute chunk c
        const uint32_t as = buf + OFF_A;
        const uint32_t bs = buf + OFF_B;

#pragma unroll
        for (int kk = 0; kk < 2; kk++) {
            const int ks = kk * 16;
            uint32_t am[2][4];
#pragma unroll
            for (int i = 0; i < 2; i++) {
                const uint32_t off =
                    ((uint32_t)(wm * 32 + i * 16 + lm_row) * LDA + ks + lm_coloff) * 2;
                ldsm_x4(am[i], as + off);
            }
            uint32_t bm[8];
#pragma unroll
            for (int jj = 0; jj < 2; jj++) {
                const uint32_t off =
                    ((uint32_t)(ks + lm_row) * LDB + wn * 32 + jj * 16 + lm_coloff) * 2;
                ldsm_x4_t(&bm[jj * 4], bs + off);
            }
#pragma unroll
            for (int i = 0; i < 2; i++)
#pragma unroll
                for (int j = 0; j < 4; j++)
                    mma_f16(acc[i][j], am[i], &bm[j * 2]);
        }
    }

    // ---- epilogue: fp16 stores
    const int er = lane >> 2;
    const int ec = (lane & 3) * 2;
#pragma unroll
    for (int i = 0; i < 2; i++) {
        const int r0 = tile_m + wm * 32 + i * 16 + er;
#pragma unroll
        for (int j = 0; j < 4; j++) {
            const int col = tile_n + wn * 32 + j * 8 + ec;
            if (r0 < N_NODES) {
                __half2 h = __floats2half2_rn(acc[i][j][0], acc[i][j][1]);
                *reinterpret_cast<__half2*>(&g_supp_h[(size_t)r0 * OUT_SIZE + col]) = h;
            }
            if (r0 + 8 < N_NODES) {
                __half2 h = __floats2half2_rn(acc[i][j][2], acc[i][j][3]);
                *reinterpret_cast<__half2*>(&g_supp_h[(size_t)(r0 + 8) * OUT_SIZE + col]) = h;
            }
        }
    }
}

// ---------------------------------------------------------------------------
// CSR build: zero -> histogram -> scan(3) -> fill
// ---------------------------------------------------------------------------
__global__ void zero_deg_kernel() {
    const int i = blockIdx.x * blockDim.x + threadIdx.x;
    if (i < N_NODES) g_deg[i] = 0;
}

__global__ void hist_kernel(const int* __restrict__ edst) {
    const int e = blockIdx.x * blockDim.x + threadIdx.x;
    if (e < N_EDGES) atomicAdd(&g_deg[edst[e]], 1);
}

__global__ __launch_bounds__(1024) void scan1_kernel() {
    __shared__ int s[1024];
    const int tid = threadIdx.x;
    const int i = blockIdx.x * 1024 + tid;
    const int v = (i < N_NODES) ? g_deg[i] : 0;
    s[tid] = v;
    __syncthreads();
#pragma unroll
    for (int d = 1; d < 1024; d <<= 1) {
        int t = (tid >= d) ? s[tid - d] : 0;
        __syncthreads();
        s[tid] += t;
        __syncthreads();
    }
    if (i < N_NODES) g_loc[i] = s[tid] - v;
    if (tid == 1023) g_bsum[blockIdx.x] = s[1023];
}

__global__ __launch_bounds__(128) void scan2_kernel() {
    __shared__ int s[128];
    const int tid = threadIdx.x;
    const int v = (tid < NBLK_SCAN) ? g_bsum[tid] : 0;
    s[tid] = v;
    __syncthreads();
#pragma unroll
    for (int d = 1; d < 128; d <<= 1) {
        int t = (tid >= d) ? s[tid - d] : 0;
        __syncthreads();
        s[tid] += t;
        __syncthreads();
    }
    g_bsum[tid] = s[tid] - v;
}

__global__ void scan3_kernel() {
    const int i = blockIdx.x * blockDim.x + threadIdx.x;
    if (i < N_NODES) {
        const int off = g_loc[i] + g_bsum[i >> 10];
        g_off[i] = off;
        g_cur[i] = off;
    }
    if (i == 0) g_off[N_NODES] = N_EDGES;
}

__global__ void fill_kernel(const float* __restrict__ ew,
                            const int* __restrict__ esrc,
                            const int* __restrict__ edst) {
    const int e = blockIdx.x * blockDim.x + threadIdx.x;
    if (e < N_EDGES) {
        const int p = atomicAdd(&g_cur[edst[e]], 1);
        g_edge[p] = make_uint2((uint32_t)esrc[e], __float_as_uint(ew[e]));
    }
}

// ---------------------------------------------------------------------------
// Aggregate: one warp per dst node. out[d] = sum supp_h[src]*w + bias.
// fp16 gather: one uint4 (8 halves) per lane per edge.
// ---------------------------------------------------------------------------
__global__ __launch_bounds__(256) void aggregate_kernel(const float* __restrict__ bias,
                                                        float* __restrict__ out) {
    const int d = (blockIdx.x * blockDim.x + threadIdx.x) >> 5;
    const int lane = threadIdx.x & 31;
    if (d >= N_NODES) return;

    const int beg = g_off[d];
    const int end = g_off[d + 1];

    float4 acc0 = reinterpret_cast<const float4*>(bias)[lane * 2];
    float4 acc1 = reinterpret_cast<const float4*>(bias)[lane * 2 + 1];

    int p = beg;
    for (; p + 1 < end; p += 2) {
        const uint2 e0 = g_edge[p];
        const uint2 e1 = g_edge[p + 1];
        const float w0 = __uint_as_float(e0.y);
        const float w1 = __uint_as_float(e1.y);
        const uint4 v0 = *reinterpret_cast<const uint4*>(
            &g_supp_h[(size_t)e0.x * OUT_SIZE + lane * 8]);
        const uint4 v1 = *reinterpret_cast<const uint4*>(
            &g_supp_h[(size_t)e1.x * OUT_SIZE + lane * 8]);

        float2 f;
        f = h2f2(v0.x); acc0.x = fmaf(f.x, w0, acc0.x); acc0.y = fmaf(f.y, w0, acc0.y);
        f = h2f2(v0.y); acc0.z = fmaf(f.x, w0, acc0.z); acc0.w = fmaf(f.y, w0, acc0.w);
        f = h2f2(v0.z); acc1.x = fmaf(f.x, w0, acc1.x); acc1.y = fmaf(f.y, w0, acc1.y);
        f = h2f2(v0.w); acc1.z = fmaf(f.x, w0, acc1.z); acc1.w = fmaf(f.y, w0, acc1.w);

        f = h2f2(v1.x); acc0.x = fmaf(f.x, w1, acc0.x); acc0.y = fmaf(f.y, w1, acc0.y);
        f = h2f2(v1.y); acc0.z = fmaf(f.x, w1, acc0.z); acc0.w = fmaf(f.y, w1, acc0.w);
        f = h2f2(v1.z); acc1.x = fmaf(f.x, w1, acc1.x); acc1.y = fmaf(f.y, w1, acc1.y);
        f = h2f2(v1.w); acc1.z = fmaf(f.x, w1, acc1.z); acc1.w = fmaf(f.y, w1, acc1.w);
    }
    if (p < end) {
        const uint2 e0 = g_edge[p];
        const float w0 = __uint_as_float(e0.y);
        const uint4 v0 = *reinterpret_cast<const uint4*>(
            &g_supp_h[(size_t)e0.x * OUT_SIZE + lane * 8]);
        float2 f;
        f = h2f2(v0.x); acc0.x = fmaf(f.x, w0, acc0.x); acc0.y = fmaf(f.y, w0, acc0.y);
        f = h2f2(v0.y); acc0.z = fmaf(f.x, w0, acc0.z); acc0.w = fmaf(f.y, w0, acc0.w);
        f = h2f2(v0.z); acc1.x = fmaf(f.x, w0, acc1.x); acc1.y = fmaf(f.y, w0, acc1.y);
        f = h2f2(v0.w); acc1.z = fmaf(f.x, w0, acc1.z); acc1.w = fmaf(f.y, w0, acc1.w);
    }

    float* op = &out[(size_t)d * OUT_SIZE + lane * 8];
    stcs_f4(op, acc0);
    stcs_f4(op + 4, acc1);
}

// ---------------------------------------------------------------------------
extern "C" void kernel_launch(void* const* d_in, const int* in_sizes, int n_in,
                              void* d_out, int out_size) {
    const float* x      = (const float*)d_in[0];
    const float* weight = (const float*)d_in[1];
    const float* bias   = (const float*)d_in[2];
    const float* ew     = (const float*)d_in[3];
    const int*   esrc   = (const int*)d_in[4];
    const int*   edst   = (const int*)d_in[5];
    float* out = (float*)d_out;

    static cudaStream_t s2 = nullptr;
    static cudaEvent_t evA = nullptr, evB = nullptr;
    if (!s2) {
        cudaStreamCreateWithFlags(&s2, cudaStreamNonBlocking);
        cudaEventCreateWithFlags(&evA, cudaEventDisableTiming);
        cudaEventCreateWithFlags(&evB, cudaEventDisableTiming);
        cudaFuncSetAttribute(gemm_hmma_kernel, cudaFuncAttributeMaxDynamicSharedMemorySize,
                             GEMM_SMEM);
    }

    // ---- fork: CSR build on s2, concurrent with GEMM on default stream
    cudaEventRecord(evA, 0);
    cudaStreamWaitEvent(s2, evA, 0);

    zero_deg_kernel<<<(N_NODES + 255) / 256, 256, 0, s2>>>();
    hist_kernel<<<(N_EDGES + 255) / 256, 256, 0, s2>>>(edst);
    scan1_kernel<<<NBLK_SCAN, 1024, 0, s2>>>();
    scan2_kernel<<<1, 128, 0, s2>>>();
    scan3_kernel<<<(N_NODES + 255) / 256, 256, 0, s2>>>();
    fill_kernel<<<(N_EDGES + 255) / 256, 256, 0, s2>>>(ew, esrc, edst);
    cudaEventRecord(evB, s2);

    // ---- main stream: prep + GEMM
    prep_w_kernel<<<IN_SIZE * OUT_SIZE / 256, 256>>>(weight);
    dim3 ggrid(OUT_SIZE / 64, (N_NODES + 127) / 128);
    gemm_hmma_kernel<<<ggrid, 256, GEMM_SMEM>>>(x);

    // ---- join, then aggregate
    cudaStreamWaitEvent(0, evB, 0);
    aggregate_kernel<<<(N_NODES * 32 + 255) / 256, 256>>>(bias, out);
}